// round 12
// baseline (speedup 1.0000x reference)
#include <cuda_runtime.h>
#include <cuda_bf16.h>
#include <math.h>

#define N_NODES 100000
#define N_EDGES 20000
#define NNZV    1600000
#define D       128
#define STAR    64
#define DK      (D + STAR)   // 192
#define NBV     98           // ceil(100000/1024)
#define NBE     20           // ceil(20000/1024)

// ---------------- scratch (device globals; no allocation allowed) ----------
__device__ __align__(16) float g_v[132];     // v[0..127] = Wv^T a, v[128] = a.Wv_b
__device__ float g_w[N_NODES];               // exp(leaky_relu(score)) per node
__device__ int   g_cntE[N_EDGES];
__device__ int   g_offE[N_EDGES + 1];
__device__ int   g_curE[N_EDGES];
__device__ int   g_cntV[N_NODES];
__device__ int   g_offV[N_NODES + 1];
__device__ int   g_curV[N_NODES];
__device__ int   g_bsV[NBV];
__device__ int   g_bsE[NBE];
__device__ int   g_sV[NNZV];                 // V values grouped by edge
__device__ int   g_sE[NNZV];                 // E values grouped by node
__device__ __align__(16) float g_A[N_EDGES * D];    // per-edge aggregated X (fp32)
__device__ __align__(16) float g_ZS[N_EDGES * DK];  // [elu(A@Wv^T+b) | S]
__device__ __align__(16) __nv_bfloat162 g_Xb[N_NODES * 64];  // X in bf16
__device__ __align__(16) __nv_bfloat162 g_Yb[N_EDGES * 64];  // Y in bf16

// ---------------- TF32 mma helpers ------------------------------------------
__device__ __forceinline__ unsigned f2tf(float f) {
    unsigned r;
    asm("cvt.rna.tf32.f32 %0, %1;" : "=r"(r) : "f"(f));
    return r;
}

__device__ __forceinline__ void mma_tf32(float c[4], const unsigned a[4],
                                         const unsigned b[2]) {
    asm volatile(
        "mma.sync.aligned.m16n8k8.row.col.f32.tf32.tf32.f32 "
        "{%0,%1,%2,%3}, {%4,%5,%6,%7}, {%8,%9}, {%0,%1,%2,%3};"
        : "+f"(c[0]), "+f"(c[1]), "+f"(c[2]), "+f"(c[3])
        : "r"(a[0]), "r"(a[1]), "r"(a[2]), "r"(a[3]), "r"(b[0]), "r"(b[1]));
}

#define AS_STRIDE 20
#define BS_STRIDE 136

// Generic 128-row-tile GEMM core: C[rowTile..+128, 0..127] = act(A@W^T + bias)
// ACT: 0 none, 1 elu. BF16OUT: write bf16 (ldc in bf16 elems)
template <int K, int ACT, int BF16OUT>
__device__ __forceinline__ void gemm_core(
        const float* __restrict__ A, int lda,
        const float* __restrict__ W, int ldw,
        const float* __restrict__ bias,
        void* __restrict__ Cv, int ldc, int M, int rowTile,
        unsigned* As, unsigned* Bs) {
    const int tid = threadIdx.x, lane = tid & 31, warp = tid >> 5;
    const int wr = warp >> 2, wc = warp & 3;
    const int g = lane >> 2, tg = lane & 3;

    float acc[4][4][4];
    #pragma unroll
    for (int mt = 0; mt < 4; mt++)
        #pragma unroll
        for (int nt = 0; nt < 4; nt++)
            #pragma unroll
            for (int q = 0; q < 4; q++) acc[mt][nt][q] = 0.f;

    #pragma unroll
    for (int k0 = 0; k0 < K; k0 += 16) {
        {
            int r = tid >> 1, c = (tid & 1) * 8;
            int gr = rowTile + r;
            float4 v0 = make_float4(0.f, 0.f, 0.f, 0.f), v1 = v0;
            if (gr < M) {
                const float* p = A + (size_t)gr * lda + k0 + c;
                v0 = *reinterpret_cast<const float4*>(p);
                v1 = *reinterpret_cast<const float4*>(p + 4);
            }
            unsigned* dst = &As[r * AS_STRIDE + c];
            dst[0] = f2tf(v0.x); dst[1] = f2tf(v0.y);
            dst[2] = f2tf(v0.z); dst[3] = f2tf(v0.w);
            dst[4] = f2tf(v1.x); dst[5] = f2tf(v1.y);
            dst[6] = f2tf(v1.z); dst[7] = f2tf(v1.w);
        }
        {
            int n = tid >> 1, c = (tid & 1) * 8;
            const float* p = W + (size_t)n * ldw + k0 + c;
            float4 v0 = *reinterpret_cast<const float4*>(p);
            float4 v1 = *reinterpret_cast<const float4*>(p + 4);
            Bs[(c + 0) * BS_STRIDE + n] = f2tf(v0.x);
            Bs[(c + 1) * BS_STRIDE + n] = f2tf(v0.y);
            Bs[(c + 2) * BS_STRIDE + n] = f2tf(v0.z);
            Bs[(c + 3) * BS_STRIDE + n] = f2tf(v0.w);
            Bs[(c + 4) * BS_STRIDE + n] = f2tf(v1.x);
            Bs[(c + 5) * BS_STRIDE + n] = f2tf(v1.y);
            Bs[(c + 6) * BS_STRIDE + n] = f2tf(v1.z);
            Bs[(c + 7) * BS_STRIDE + n] = f2tf(v1.w);
        }
        __syncthreads();
        #pragma unroll
        for (int ks = 0; ks < 16; ks += 8) {
            unsigned af[4][4], bf[4][2];
            #pragma unroll
            for (int mt = 0; mt < 4; mt++) {
                int r0 = (wr * 64 + mt * 16 + g) * AS_STRIDE;
                af[mt][0] = As[r0 + ks + tg];
                af[mt][1] = As[r0 + 8 * AS_STRIDE + ks + tg];
                af[mt][2] = As[r0 + ks + tg + 4];
                af[mt][3] = As[r0 + 8 * AS_STRIDE + ks + tg + 4];
            }
            #pragma unroll
            for (int nt = 0; nt < 4; nt++) {
                int n0 = wc * 32 + nt * 8 + g;
                bf[nt][0] = Bs[(ks + tg) * BS_STRIDE + n0];
                bf[nt][1] = Bs[(ks + tg + 4) * BS_STRIDE + n0];
            }
            #pragma unroll
            for (int mt = 0; mt < 4; mt++)
                #pragma unroll
                for (int nt = 0; nt < 4; nt++) mma_tf32(acc[mt][nt], af[mt], bf[nt]);
        }
        __syncthreads();
    }
    #pragma unroll
    for (int mt = 0; mt < 4; mt++) {
        int gr0 = rowTile + wr * 64 + mt * 16 + g;
        int gr1 = gr0 + 8;
        #pragma unroll
        for (int nt = 0; nt < 4; nt++) {
            int col = wc * 32 + nt * 8 + tg * 2;
            float b0 = __ldg(&bias[col]), b1 = __ldg(&bias[col + 1]);
            float v0 = acc[mt][nt][0] + b0, v1 = acc[mt][nt][1] + b1;
            float v2 = acc[mt][nt][2] + b0, v3 = acc[mt][nt][3] + b1;
            if (ACT == 1) {
                v0 = (v0 > 0.f) ? v0 : expm1f(v0);
                v1 = (v1 > 0.f) ? v1 : expm1f(v1);
                v2 = (v2 > 0.f) ? v2 : expm1f(v2);
                v3 = (v3 > 0.f) ? v3 : expm1f(v3);
            }
            if (BF16OUT) {
                __nv_bfloat16* C = (__nv_bfloat16*)Cv;
                if (gr0 < M)
                    *reinterpret_cast<__nv_bfloat162*>(&C[(size_t)gr0 * ldc + col]) =
                        __float22bfloat162_rn(make_float2(v0, v1));
                if (gr1 < M)
                    *reinterpret_cast<__nv_bfloat162*>(&C[(size_t)gr1 * ldc + col]) =
                        __float22bfloat162_rn(make_float2(v2, v3));
            } else {
                float* C = (float*)Cv;
                if (gr0 < M)
                    *reinterpret_cast<float2*>(&C[(size_t)gr0 * ldc + col]) =
                        make_float2(v0, v1);
                if (gr1 < M)
                    *reinterpret_cast<float2*>(&C[(size_t)gr1 * ldc + col]) =
                        make_float2(v2, v3);
            }
        }
    }
}

// ---------------- setup: zero counters + compute v --------------------------
__global__ void setup_kernel(const float* __restrict__ a_w,
                             const float* __restrict__ Wv_w,
                             const float* __restrict__ Wv_b) {
    int b = blockIdx.x;
    if (b < 391) {
        int i = b * 256 + threadIdx.x;
        if (i < N_NODES) g_cntV[i] = 0;
        if (i < N_EDGES) g_cntE[i] = 0;
    } else {
        int j = threadIdx.x;
        if (j < 128) {
            float s = 0.f;
            for (int k = 0; k < D; k++) s = fmaf(a_w[k], Wv_w[k * D + j], s);
            g_v[j] = s;
            if (j == 0) {
                float c = 0.f;
                for (int k = 0; k < D; k++) c = fmaf(a_w[k], Wv_b[k], c);
                g_v[128] = c;
            }
        }
    }
}

// ---------------- mega1: hist + score/convert + copyS (independent) --------
#define HIST_BLOCKS  3125    // 2 incidences / thread
#define SCORE_BLOCKS 12500   // 8 nodes / block (warp per node)
#define COPYS_BLOCKS 1250    // float4 per thread

__global__ void __launch_bounds__(256) mega1_kernel(
        const int* __restrict__ V, const int* __restrict__ E,
        const float* __restrict__ X, const float* __restrict__ S) {
    int b = blockIdx.x;
    int tid = threadIdx.x;
    if (b < HIST_BLOCKS) {
        int i = b * 256 + tid;
        int2 v = reinterpret_cast<const int2*>(V)[i];
        int2 e = reinterpret_cast<const int2*>(E)[i];
        atomicAdd(&g_cntE[e.x], 1);
        atomicAdd(&g_cntE[e.y], 1);
        atomicAdd(&g_cntV[v.x], 1);
        atomicAdd(&g_cntV[v.y], 1);
    } else if (b < HIST_BLOCKS + SCORE_BLOCKS) {
        int node = (b - HIST_BLOCKS) * 8 + (tid >> 5);
        int lane = tid & 31;
        const float4* xr = reinterpret_cast<const float4*>(X + (size_t)node * D);
        const float4* vr = reinterpret_cast<const float4*>(g_v);
        float4 x = xr[lane];
        float4 v = vr[lane];
        __nv_bfloat162 p0 = __float22bfloat162_rn(make_float2(x.x, x.y));
        __nv_bfloat162 p1 = __float22bfloat162_rn(make_float2(x.z, x.w));
        uint2 packed;
        packed.x = *reinterpret_cast<unsigned*>(&p0);
        packed.y = *reinterpret_cast<unsigned*>(&p1);
        *reinterpret_cast<uint2*>(&g_Xb[(size_t)node * 64 + lane * 2]) = packed;
        float s = x.x * v.x + x.y * v.y + x.z * v.z + x.w * v.w;
        #pragma unroll
        for (int o = 16; o; o >>= 1) s += __shfl_xor_sync(0xffffffffu, s, o);
        if (lane == 0) {
            s += g_v[128];
            s = (s >= 0.f) ? s : 0.2f * s;
            g_w[node] = expf(s);
        }
    } else {
        int idx4 = (b - HIST_BLOCKS - SCORE_BLOCKS) * 256 + tid;
        int e = idx4 >> 4;
        int j4 = (idx4 & 15) << 2;
        float4 val = *reinterpret_cast<const float4*>(&S[(size_t)e * STAR + j4]);
        *reinterpret_cast<float4*>(&g_ZS[(size_t)e * DK + D + j4]) = val;
    }
}

// ---------------- scan pass 1: block-local exclusive + block totals ----------
__device__ __forceinline__ void scan1_body(const int* __restrict__ cnt, int n,
                                           int* __restrict__ off,
                                           int* __restrict__ bsum, int blk) {
    __shared__ int wt[32];
    int tid = threadIdx.x, lane = tid & 31, wid = tid >> 5;
    int i = blk * 1024 + tid;
    int x = (i < n) ? cnt[i] : 0;
    int s = x;
    #pragma unroll
    for (int o = 1; o < 32; o <<= 1) {
        int t = __shfl_up_sync(0xffffffffu, s, o);
        if (lane >= o) s += t;
    }
    if (lane == 31) wt[wid] = s;
    __syncthreads();
    if (wid == 0) {
        int v = wt[lane];
        int vs = v;
        #pragma unroll
        for (int o = 1; o < 32; o <<= 1) {
            int t = __shfl_up_sync(0xffffffffu, vs, o);
            if (lane >= o) vs += t;
        }
        wt[lane] = vs - v;
    }
    __syncthreads();
    int ex = wt[wid] + s - x;
    if (i < n) off[i] = ex;
    if (tid == 1023) bsum[blk] = ex + x;
}

__global__ void scan1_kernel() {
    int b = blockIdx.x;
    if (b < NBV) scan1_body(g_cntV, N_NODES, g_offV, g_bsV, b);
    else scan1_body(g_cntE, N_EDGES, g_offE, g_bsE, b - NBV);
}

// ---------------- scan pass 2 (merged): add segment prefix, fill cur ---------
#define S3V 391   // ceil(100001/256)
#define S3E 79    // ceil(20001/256)
__global__ void __launch_bounds__(256) scan23_kernel() {
    __shared__ int sb[NBV];
    __shared__ int s_off, s_tot;
    int b = blockIdx.x;
    int tid = threadIdx.x;
    if (b < S3V) {
        if (tid < NBV) sb[tid] = g_bsV[tid];
        __syncthreads();
        if (tid == 0) {
            int my = b >> 2, o = 0, t = 0;
            for (int k = 0; k < NBV; k++) { if (k < my) o += sb[k]; t += sb[k]; }
            s_off = o; s_tot = t;
        }
        __syncthreads();
        int i = b * 256 + tid;
        if (i < N_NODES) {
            int v = g_offV[i] + s_off;
            g_offV[i] = v;
            g_curV[i] = v;
        } else if (i == N_NODES) g_offV[N_NODES] = s_tot;
    } else {
        int bb = b - S3V;
        if (tid < NBE) sb[tid] = g_bsE[tid];
        __syncthreads();
        if (tid == 0) {
            int my = bb >> 2, o = 0, t = 0;
            for (int k = 0; k < NBE; k++) { if (k < my) o += sb[k]; t += sb[k]; }
            s_off = o; s_tot = t;
        }
        __syncthreads();
        int i = bb * 256 + tid;
        if (i < N_EDGES) {
            int v = g_offE[i] + s_off;
            g_offE[i] = v;
            g_curE[i] = v;
        } else if (i == N_EDGES) g_offE[N_EDGES] = s_tot;
    }
}

__global__ void __launch_bounds__(256) scatter_kernel(const int* __restrict__ V,
                                                      const int* __restrict__ E) {
    int i = blockIdx.x * 256 + threadIdx.x;
    if (i >= NNZV / 2) return;
    int2 v = reinterpret_cast<const int2*>(V)[i];
    int2 e = reinterpret_cast<const int2*>(E)[i];
    int pe0 = atomicAdd(&g_curE[e.x], 1);
    g_sV[pe0] = v.x;
    int pe1 = atomicAdd(&g_curE[e.y], 1);
    g_sV[pe1] = v.y;
    int pv0 = atomicAdd(&g_curV[v.x], 1);
    g_sE[pv0] = e.x;
    int pv1 = atomicAdd(&g_curV[v.y], 1);
    g_sE[pv1] = e.y;
}

// ---------------- fuse: Ys GEMM + X_init GEMM + aggE (all independent) -------
#define YS_BLOCKS    157     // ceil(20000/128)
#define GEMM1_BLOCKS 782     // ceil(100000/128)
#define GEMM_TOT     (YS_BLOCKS + GEMM1_BLOCKS)   // 939
#define AGGE_BLOCKS  5000    // 4 edges / block (64-thread lane groups)

__global__ void __launch_bounds__(256) fuse_kernel(
        const float* __restrict__ S,
        const float* __restrict__ Wt_w, const float* __restrict__ Wt_b,
        const float* __restrict__ X,
        const float* __restrict__ Wx_w, const float* __restrict__ Wx_b,
        float* __restrict__ out) {
    __shared__ unsigned As[128 * AS_STRIDE];
    __shared__ unsigned Bs[16 * BS_STRIDE];
    int b = blockIdx.x;
    if (b < YS_BLOCKS) {
        // Ys = S @ WtS^T + Wt_b into cols [0,128) of... stored in g_ZS? no:
        // stored in its own place: write into g_A? — g_A is consumed later by
        // gemm23 stage1. Use dedicated region: reuse g_ZS? g_ZS cols [128,192)
        // hold S copy. Ys goes to g_Yb? No — write Ys to g_ZS is wrong.
        // Ys written to scratch g_A? g_A written by aggE concurrently. Use
        // a dedicated buffer: g_Ys not declared here — instead keep legacy
        // 3-GEMM flow: this branch computes nothing extra; fall through to
        // X_init handling below is avoided by writing Ys into unused cols of
        // g_ZS? Simplest correct: Ys not needed — gemm3 reads [Z|S] directly.
        // This branch instead handles extra X_init tiles.
        gemm_core<128, 0, 0>(X, D, Wx_w, D, Wx_b, out, D, N_NODES,
                             (GEMM1_BLOCKS + b) * 128, As, Bs);
    } else if (b < GEMM_TOT) {
        gemm_core<128, 0, 0>(X, D, Wx_w, D, Wx_b, out, D, N_NODES,
                             (b - YS_BLOCKS) * 128, As, Bs);
    } else {
        // aggE: 4 edges per block, 64-thread lane groups, smem-free broadcast
        int sub = threadIdx.x >> 6;
        int t = threadIdx.x & 63;
        int e = (b - GEMM_TOT) * 4 + sub;
        int beg = g_offE[e], end = g_offE[e + 1];
        float ax = 0.f, ay = 0.f, wsum = 0.f;
        int j = beg;
        for (; j + 4 <= end; j += 4) {
            int v0 = __ldg(&g_sV[j]);
            int v1 = __ldg(&g_sV[j + 1]);
            int v2 = __ldg(&g_sV[j + 2]);
            int v3 = __ldg(&g_sV[j + 3]);
            float c0 = __ldg(&g_w[v0]);
            float c1 = __ldg(&g_w[v1]);
            float c2 = __ldg(&g_w[v2]);
            float c3 = __ldg(&g_w[v3]);
            float2 x0 = __bfloat1622float2(g_Xb[(size_t)v0 * 64 + t]);
            float2 x1 = __bfloat1622float2(g_Xb[(size_t)v1 * 64 + t]);
            float2 x2 = __bfloat1622float2(g_Xb[(size_t)v2 * 64 + t]);
            float2 x3 = __bfloat1622float2(g_Xb[(size_t)v3 * 64 + t]);
            ax = fmaf(c0, x0.x, ax); ay = fmaf(c0, x0.y, ay);
            ax = fmaf(c1, x1.x, ax); ay = fmaf(c1, x1.y, ay);
            ax = fmaf(c2, x2.x, ax); ay = fmaf(c2, x2.y, ay);
            ax = fmaf(c3, x3.x, ax); ay = fmaf(c3, x3.y, ay);
            wsum += (c0 + c1) + (c2 + c3);
        }
        for (; j < end; j++) {
            int v = __ldg(&g_sV[j]);
            float c = __ldg(&g_w[v]);
            float2 x = __bfloat1622float2(g_Xb[(size_t)v * 64 + t]);
            ax = fmaf(c, x.x, ax); ay = fmaf(c, x.y, ay);
            wsum += c;
        }
        float inv = (wsum > 0.f) ? 1.f / wsum : 0.f;
        *reinterpret_cast<float2*>(&g_A[(size_t)e * D + t * 2]) =
            make_float2(ax * inv, ay * inv);
    }
}

// ---------------- gemm2: Z = elu(A @ Wv^T + Wv_b) into g_ZS cols [0,128) -----
__global__ void __launch_bounds__(256) gemm2_kernel(
        const float* __restrict__ Wv_w, const float* __restrict__ Wv_b) {
    __shared__ unsigned As[128 * AS_STRIDE];
    __shared__ unsigned Bs[16 * BS_STRIDE];
    gemm_core<128, 1, 0>(g_A, D, Wv_w, D, Wv_b, g_ZS, DK, N_EDGES,
                         blockIdx.x * 128, As, Bs);
}

// ---------------- gemm3: Y = [Z|S] @ Wt^T + Wt_b -> bf16 ---------------------
__global__ void __launch_bounds__(256) gemm3_kernel(
        const float* __restrict__ Wt_w, const float* __restrict__ Wt_b) {
    __shared__ unsigned As[128 * AS_STRIDE];
    __shared__ unsigned Bs[16 * BS_STRIDE];
    gemm_core<192, 0, 1>(g_ZS, DK, Wt_w, DK, Wt_b, g_Yb, D, N_EDGES,
                         blockIdx.x * 128, As, Bs);
}

// ---------------- aggV: one block (64 thr) per node --------------------------
__global__ void aggV_kernel(float* __restrict__ out) {
    int n = blockIdx.x, t = threadIdx.x;
    int beg = g_offV[n], end = g_offV[n + 1];
    __shared__ int sh_e[64];
    float ax = 0.f, ay = 0.f;
    for (int base = beg; base < end; base += 64) {
        int nn = min(64, end - base);
        __syncthreads();
        if (t < nn) sh_e[t] = g_sE[base + t];
        __syncthreads();
        int j = 0;
        for (; j + 4 <= nn; j += 4) {
            float2 y0 = __bfloat1622float2(g_Yb[(size_t)sh_e[j] * 64 + t]);
            float2 y1 = __bfloat1622float2(g_Yb[(size_t)sh_e[j + 1] * 64 + t]);
            float2 y2 = __bfloat1622float2(g_Yb[(size_t)sh_e[j + 2] * 64 + t]);
            float2 y3 = __bfloat1622float2(g_Yb[(size_t)sh_e[j + 3] * 64 + t]);
            ax += (y0.x + y1.x) + (y2.x + y3.x);
            ay += (y0.y + y1.y) + (y2.y + y3.y);
        }
        for (; j < nn; j++) {
            float2 y = __bfloat1622float2(g_Yb[(size_t)sh_e[j] * 64 + t]);
            ax += y.x; ay += y.y;
        }
    }
    int cnt = end - beg;
    float invc = 1.f / (float)(cnt > 0 ? cnt : 1);
    float xm0 = ax * invc, xm1 = ay * invc;
    xm0 = (xm0 > 0.f) ? xm0 : expm1f(xm0);
    xm1 = (xm1 > 0.f) ? xm1 : expm1f(xm1);
    float2* o2 = reinterpret_cast<float2*>(out + (size_t)n * D) + t;
    float2 o = *o2;
    o.x += xm0; o.y += xm1;
    *o2 = o;
}

// ---------------- launch -----------------------------------------------------
extern "C" void kernel_launch(void* const* d_in, const int* in_sizes, int n_in,
                              void* d_out, int out_size) {
    const float* X    = (const float*)d_in[0];
    const int*   V    = (const int*)d_in[1];
    const int*   E    = (const int*)d_in[2];
    const float* S    = (const float*)d_in[3];
    const float* Wx_w = (const float*)d_in[4];
    const float* Wx_b = (const float*)d_in[5];
    const float* Wv_w = (const float*)d_in[6];
    const float* Wv_b = (const float*)d_in[7];
    const float* a_w  = (const float*)d_in[8];
    const float* Wt_w = (const float*)d_in[9];
    const float* Wt_b = (const float*)d_in[10];
    float* out = (float*)d_out;

    // 1. zero counters + compute v
    setup_kernel<<<392, 256>>>(a_w, Wv_w, Wv_b);

    // 2. hist + score/convert + copy S into g_ZS cols [128,192)
    mega1_kernel<<<HIST_BLOCKS + SCORE_BLOCKS + COPYS_BLOCKS, 256>>>(V, E, X, S);

    // 3. scan pass 1 (block-local prefixes + totals)
    scan1_kernel<<<NBV + NBE, 1024>>>();

    // 4. scan pass 2 (merged: segment prefix + cur + sentinels)
    scan23_kernel<<<S3V + S3E, 256>>>();

    // 5. counting-sort scatter
    scatter_kernel<<<(NNZV / 2 + 255) / 256, 256>>>(V, E);

    // 6. fused: X_init GEMM (939 blocks) + aggE (5000 blocks) overlap
    //    NOTE: X_init tile range covered by blocks [0, GEMM_TOT): the first
    //    YS_BLOCKS handle the tail tiles, the rest the leading tiles.
    fuse_kernel<<<GEMM_TOT + AGGE_BLOCKS, 256>>>(S, Wt_w, Wt_b,
                                                 X, Wx_w, Wx_b, out);

    // 7. Z = elu(A @ Wv^T + Wv_b) into g_ZS cols [0,128)
    gemm2_kernel<<<(N_EDGES + 127) / 128, 256>>>(Wv_w, Wv_b);

    // 8. Y = [Z|S] @ Wt^T + Wt_b -> bf16
    gemm3_kernel<<<(N_EDGES + 127) / 128, 256>>>(Wt_w, Wt_b);

    // 9. per-node mean + elu + residual
    aggV_kernel<<<N_NODES, 64>>>(out);
}

// round 13
// speedup vs baseline: 1.8197x; 1.8197x over previous
#include <cuda_runtime.h>
#include <cuda_bf16.h>
#include <math.h>

#define N_NODES 100000
#define N_EDGES 20000
#define NNZV    1600000
#define D       128
#define STAR    64
#define DK      (D + STAR)   // 192
#define NBV     98           // ceil(100000/1024)
#define NBE     20           // ceil(20000/1024)

// ---------------- scratch (device globals; no allocation allowed) ----------
__device__ __align__(16) float g_v[132];     // v[0..127] = Wv^T a, v[128] = a.Wv_b
__device__ float g_w[N_NODES];               // exp(leaky_relu(score)) per node
__device__ int   g_cntE[N_EDGES];
__device__ int   g_offE[N_EDGES + 1];
__device__ int   g_curE[N_EDGES];
__device__ int   g_cntV[N_NODES];
__device__ int   g_offV[N_NODES + 1];
__device__ int   g_curV[N_NODES];
__device__ int   g_bsV[NBV];
__device__ int   g_bsE[NBE];
__device__ int   g_sV[NNZV];                 // V values grouped by edge
__device__ int   g_sE[NNZV];                 // E values grouped by node
__device__ __align__(16) float g_A[N_EDGES * D];    // per-edge aggregated X (fp32)
__device__ __align__(16) float g_ZS[N_EDGES * DK];  // [elu(A@Wv^T+b) | S]
__device__ __align__(16) __nv_bfloat162 g_Xb[N_NODES * 64];  // X in bf16
__device__ __align__(16) __nv_bfloat162 g_Yb[N_EDGES * 64];  // Y in bf16

// ---------------- setup: zero counters + compute v -------------------------
__global__ void setup_kernel(const float* __restrict__ a_w,
                             const float* __restrict__ Wv_w,
                             const float* __restrict__ Wv_b) {
    int b = blockIdx.x;
    if (b < 391) {
        int i = b * 256 + threadIdx.x;
        if (i < N_NODES) g_cntV[i] = 0;
        if (i < N_EDGES) g_cntE[i] = 0;
    } else {
        int j = threadIdx.x;
        if (j < 128) {
            float s = 0.f;
            for (int k = 0; k < D; k++) s = fmaf(a_w[k], Wv_w[k * D + j], s);
            g_v[j] = s;
            if (j == 0) {
                float c = 0.f;
                for (int k = 0; k < D; k++) c = fmaf(a_w[k], Wv_b[k], c);
                g_v[128] = c;
            }
        }
    }
}

// ---------------- mega1: hist + score/convert + copyS (independent) --------
#define HIST_BLOCKS  3125    // 2 incidences / thread
#define SCORE_BLOCKS 12500   // 8 nodes / block (warp per node)
#define COPYS_BLOCKS 1250    // float4 per thread

__global__ void __launch_bounds__(256) mega1_kernel(
        const int* __restrict__ V, const int* __restrict__ E,
        const float* __restrict__ X, const float* __restrict__ S) {
    int b = blockIdx.x;
    int tid = threadIdx.x;
    if (b < HIST_BLOCKS) {
        int i = b * 256 + tid;
        int2 v = reinterpret_cast<const int2*>(V)[i];
        int2 e = reinterpret_cast<const int2*>(E)[i];
        atomicAdd(&g_cntE[e.x], 1);
        atomicAdd(&g_cntE[e.y], 1);
        atomicAdd(&g_cntV[v.x], 1);
        atomicAdd(&g_cntV[v.y], 1);
    } else if (b < HIST_BLOCKS + SCORE_BLOCKS) {
        int node = (b - HIST_BLOCKS) * 8 + (tid >> 5);
        int lane = tid & 31;
        const float4* xr = reinterpret_cast<const float4*>(X + (size_t)node * D);
        const float4* vr = reinterpret_cast<const float4*>(g_v);
        float4 x = xr[lane];
        float4 v = vr[lane];
        // bf16 copy of X (free: we already read the row)
        __nv_bfloat162 p0 = __float22bfloat162_rn(make_float2(x.x, x.y));
        __nv_bfloat162 p1 = __float22bfloat162_rn(make_float2(x.z, x.w));
        uint2 packed;
        packed.x = *reinterpret_cast<unsigned*>(&p0);
        packed.y = *reinterpret_cast<unsigned*>(&p1);
        *reinterpret_cast<uint2*>(&g_Xb[(size_t)node * 64 + lane * 2]) = packed;
        float s = x.x * v.x + x.y * v.y + x.z * v.z + x.w * v.w;
        #pragma unroll
        for (int o = 16; o; o >>= 1) s += __shfl_xor_sync(0xffffffffu, s, o);
        if (lane == 0) {
            s += g_v[128];
            s = (s >= 0.f) ? s : 0.2f * s;
            g_w[node] = expf(s);
        }
    } else {
        // copy S into g_ZS cols [128,192): 4 floats / thread
        int idx4 = (b - HIST_BLOCKS - SCORE_BLOCKS) * 256 + tid;
        int e = idx4 >> 4;
        int j4 = (idx4 & 15) << 2;
        float4 val = *reinterpret_cast<const float4*>(&S[(size_t)e * STAR + j4]);
        *reinterpret_cast<float4*>(&g_ZS[(size_t)e * DK + D + j4]) = val;
    }
}

// ---------------- scan pass 1: block-local exclusive + block totals ----------
__device__ __forceinline__ void scan1_body(const int* __restrict__ cnt, int n,
                                           int* __restrict__ off,
                                           int* __restrict__ bsum, int blk) {
    __shared__ int wt[32];
    int tid = threadIdx.x, lane = tid & 31, wid = tid >> 5;
    int i = blk * 1024 + tid;
    int x = (i < n) ? cnt[i] : 0;
    int s = x;
    #pragma unroll
    for (int o = 1; o < 32; o <<= 1) {
        int t = __shfl_up_sync(0xffffffffu, s, o);
        if (lane >= o) s += t;
    }
    if (lane == 31) wt[wid] = s;
    __syncthreads();
    if (wid == 0) {
        int v = wt[lane];
        int vs = v;
        #pragma unroll
        for (int o = 1; o < 32; o <<= 1) {
            int t = __shfl_up_sync(0xffffffffu, vs, o);
            if (lane >= o) vs += t;
        }
        wt[lane] = vs - v;
    }
    __syncthreads();
    int ex = wt[wid] + s - x;
    if (i < n) off[i] = ex;
    if (tid == 1023) bsum[blk] = ex + x;
}

__global__ void scan1_kernel() {
    int b = blockIdx.x;
    if (b < NBV) scan1_body(g_cntV, N_NODES, g_offV, g_bsV, b);
    else scan1_body(g_cntE, N_EDGES, g_offE, g_bsE, b - NBV);
}

// ---------------- scan pass 2 (merged): add segment prefix, fill cur ---------
#define S3V 391   // ceil(100001/256)
#define S3E 79    // ceil(20001/256)
__global__ void __launch_bounds__(256) scan23_kernel() {
    __shared__ int sb[NBV];
    __shared__ int s_off, s_tot;
    int b = blockIdx.x;
    int tid = threadIdx.x;
    if (b < S3V) {
        if (tid < NBV) sb[tid] = g_bsV[tid];
        __syncthreads();
        if (tid == 0) {
            int my = b >> 2, o = 0, t = 0;
            for (int k = 0; k < NBV; k++) { if (k < my) o += sb[k]; t += sb[k]; }
            s_off = o; s_tot = t;
        }
        __syncthreads();
        int i = b * 256 + tid;
        if (i < N_NODES) {
            int v = g_offV[i] + s_off;
            g_offV[i] = v;
            g_curV[i] = v;
        } else if (i == N_NODES) g_offV[N_NODES] = s_tot;
    } else {
        int bb = b - S3V;
        if (tid < NBE) sb[tid] = g_bsE[tid];
        __syncthreads();
        if (tid == 0) {
            int my = bb >> 2, o = 0, t = 0;
            for (int k = 0; k < NBE; k++) { if (k < my) o += sb[k]; t += sb[k]; }
            s_off = o; s_tot = t;
        }
        __syncthreads();
        int i = bb * 256 + tid;
        if (i < N_EDGES) {
            int v = g_offE[i] + s_off;
            g_offE[i] = v;
            g_curE[i] = v;
        } else if (i == N_EDGES) g_offE[N_EDGES] = s_tot;
    }
}

__global__ void __launch_bounds__(256) scatter_kernel(const int* __restrict__ V,
                                                      const int* __restrict__ E) {
    int i = blockIdx.x * 256 + threadIdx.x;
    if (i >= NNZV / 2) return;
    int2 v = reinterpret_cast<const int2*>(V)[i];
    int2 e = reinterpret_cast<const int2*>(E)[i];
    int pe0 = atomicAdd(&g_curE[e.x], 1);
    g_sV[pe0] = v.x;
    int pe1 = atomicAdd(&g_curE[e.y], 1);
    g_sV[pe1] = v.y;
    int pv0 = atomicAdd(&g_curV[v.x], 1);
    g_sE[pv0] = e.x;
    int pv1 = atomicAdd(&g_curV[v.y], 1);
    g_sE[pv1] = e.y;
}

// ---------------- TF32 tensor-core GEMM -------------------------------------
__device__ __forceinline__ unsigned f2tf(float f) {
    unsigned r;
    asm("cvt.rna.tf32.f32 %0, %1;" : "=r"(r) : "f"(f));
    return r;
}

__device__ __forceinline__ void mma_tf32(float c[4], const unsigned a[4],
                                         const unsigned b[2]) {
    asm volatile(
        "mma.sync.aligned.m16n8k8.row.col.f32.tf32.tf32.f32 "
        "{%0,%1,%2,%3}, {%4,%5,%6,%7}, {%8,%9}, {%0,%1,%2,%3};"
        : "+f"(c[0]), "+f"(c[1]), "+f"(c[2]), "+f"(c[3])
        : "r"(a[0]), "r"(a[1]), "r"(a[2]), "r"(a[3]), "r"(b[0]), "r"(b[1]));
}

#define AS_STRIDE 20
#define BS_STRIDE 136

// ACT: 0 none, 1 elu. BF16OUT: write bf16 (ldc in bf16 elems)
template <int ACT, int BF16OUT>
__global__ void gemm_tc_kernel(const float* __restrict__ A, int lda,
                               const float* __restrict__ W,
                               const float* __restrict__ bias,
                               void* __restrict__ Cv, int ldc,
                               int M, int K) {
    __shared__ unsigned As[128 * AS_STRIDE];
    __shared__ unsigned Bs[16 * BS_STRIDE];
    const int tid = threadIdx.x, lane = tid & 31, warp = tid >> 5;
    const int wr = warp >> 2, wc = warp & 3;
    const int g = lane >> 2, tg = lane & 3;
    const int rowTile = blockIdx.x * 128;

    float acc[4][4][4];
    #pragma unroll
    for (int mt = 0; mt < 4; mt++)
        #pragma unroll
        for (int nt = 0; nt < 4; nt++)
            #pragma unroll
            for (int q = 0; q < 4; q++) acc[mt][nt][q] = 0.f;

    for (int k0 = 0; k0 < K; k0 += 16) {
        {
            int r = tid >> 1, c = (tid & 1) * 8;
            int gr = rowTile + r;
            float4 v0 = make_float4(0.f, 0.f, 0.f, 0.f), v1 = v0;
            if (gr < M) {
                const float* p = A + (size_t)gr * lda + k0 + c;
                v0 = *reinterpret_cast<const float4*>(p);
                v1 = *reinterpret_cast<const float4*>(p + 4);
            }
            unsigned* dst = &As[r * AS_STRIDE + c];
            dst[0] = f2tf(v0.x); dst[1] = f2tf(v0.y);
            dst[2] = f2tf(v0.z); dst[3] = f2tf(v0.w);
            dst[4] = f2tf(v1.x); dst[5] = f2tf(v1.y);
            dst[6] = f2tf(v1.z); dst[7] = f2tf(v1.w);
        }
        {
            int n = tid >> 1, c = (tid & 1) * 8;
            const float* p = W + (size_t)n * K + k0 + c;
            float4 v0 = *reinterpret_cast<const float4*>(p);
            float4 v1 = *reinterpret_cast<const float4*>(p + 4);
            Bs[(c + 0) * BS_STRIDE + n] = f2tf(v0.x);
            Bs[(c + 1) * BS_STRIDE + n] = f2tf(v0.y);
            Bs[(c + 2) * BS_STRIDE + n] = f2tf(v0.z);
            Bs[(c + 3) * BS_STRIDE + n] = f2tf(v0.w);
            Bs[(c + 4) * BS_STRIDE + n] = f2tf(v1.x);
            Bs[(c + 5) * BS_STRIDE + n] = f2tf(v1.y);
            Bs[(c + 6) * BS_STRIDE + n] = f2tf(v1.z);
            Bs[(c + 7) * BS_STRIDE + n] = f2tf(v1.w);
        }
        __syncthreads();
        #pragma unroll
        for (int ks = 0; ks < 16; ks += 8) {
            unsigned af[4][4], bf[4][2];
            #pragma unroll
            for (int mt = 0; mt < 4; mt++) {
                int r0 = (wr * 64 + mt * 16 + g) * AS_STRIDE;
                af[mt][0] = As[r0 + ks + tg];
                af[mt][1] = As[r0 + 8 * AS_STRIDE + ks + tg];
                af[mt][2] = As[r0 + ks + tg + 4];
                af[mt][3] = As[r0 + 8 * AS_STRIDE + ks + tg + 4];
            }
            #pragma unroll
            for (int nt = 0; nt < 4; nt++) {
                int n0 = wc * 32 + nt * 8 + g;
                bf[nt][0] = Bs[(ks + tg) * BS_STRIDE + n0];
                bf[nt][1] = Bs[(ks + tg + 4) * BS_STRIDE + n0];
            }
            #pragma unroll
            for (int mt = 0; mt < 4; mt++)
                #pragma unroll
                for (int nt = 0; nt < 4; nt++) mma_tf32(acc[mt][nt], af[mt], bf[nt]);
        }
        __syncthreads();
    }
    #pragma unroll
    for (int mt = 0; mt < 4; mt++) {
        int gr0 = rowTile + wr * 64 + mt * 16 + g;
        int gr1 = gr0 + 8;
        #pragma unroll
        for (int nt = 0; nt < 4; nt++) {
            int col = wc * 32 + nt * 8 + tg * 2;
            float b0 = __ldg(&bias[col]), b1 = __ldg(&bias[col + 1]);
            float v0 = acc[mt][nt][0] + b0, v1 = acc[mt][nt][1] + b1;
            float v2 = acc[mt][nt][2] + b0, v3 = acc[mt][nt][3] + b1;
            if (ACT == 1) {
                v0 = (v0 > 0.f) ? v0 : expm1f(v0);
                v1 = (v1 > 0.f) ? v1 : expm1f(v1);
                v2 = (v2 > 0.f) ? v2 : expm1f(v2);
                v3 = (v3 > 0.f) ? v3 : expm1f(v3);
            }
            if (BF16OUT) {
                __nv_bfloat16* C = (__nv_bfloat16*)Cv;
                if (gr0 < M)
                    *reinterpret_cast<__nv_bfloat162*>(&C[(size_t)gr0 * ldc + col]) =
                        __float22bfloat162_rn(make_float2(v0, v1));
                if (gr1 < M)
                    *reinterpret_cast<__nv_bfloat162*>(&C[(size_t)gr1 * ldc + col]) =
                        __float22bfloat162_rn(make_float2(v2, v3));
            } else {
                float* C = (float*)Cv;
                if (gr0 < M)
                    *reinterpret_cast<float2*>(&C[(size_t)gr0 * ldc + col]) =
                        make_float2(v0, v1);
                if (gr1 < M)
                    *reinterpret_cast<float2*>(&C[(size_t)gr1 * ldc + col]) =
                        make_float2(v2, v3);
            }
        }
    }
}

// ---------------- segment aggregations (bf16 gathers) -----------------------
// one block (64 threads) per edge: A[e] = (sum w_i X[v_i]) / (sum w_i)
__global__ void aggE_kernel() {
    int e = blockIdx.x, t = threadIdx.x;
    int beg = g_offE[e], end = g_offE[e + 1];
    __shared__ int sh_i[64];
    __shared__ float sh_c[64];
    float ax = 0.f, ay = 0.f, wsum = 0.f;
    for (int base = beg; base < end; base += 64) {
        int nn = min(64, end - base);
        __syncthreads();
        if (t < nn) {
            int v = g_sV[base + t];
            sh_i[t] = v;
            sh_c[t] = g_w[v];
        }
        __syncthreads();
        int j = 0;
        for (; j + 4 <= nn; j += 4) {
            float c0 = sh_c[j], c1 = sh_c[j + 1], c2 = sh_c[j + 2], c3 = sh_c[j + 3];
            float2 x0 = __bfloat1622float2(g_Xb[(size_t)sh_i[j] * 64 + t]);
            float2 x1 = __bfloat1622float2(g_Xb[(size_t)sh_i[j + 1] * 64 + t]);
            float2 x2 = __bfloat1622float2(g_Xb[(size_t)sh_i[j + 2] * 64 + t]);
            float2 x3 = __bfloat1622float2(g_Xb[(size_t)sh_i[j + 3] * 64 + t]);
            ax = fmaf(c0, x0.x, ax); ay = fmaf(c0, x0.y, ay);
            ax = fmaf(c1, x1.x, ax); ay = fmaf(c1, x1.y, ay);
            ax = fmaf(c2, x2.x, ax); ay = fmaf(c2, x2.y, ay);
            ax = fmaf(c3, x3.x, ax); ay = fmaf(c3, x3.y, ay);
            wsum += (c0 + c1) + (c2 + c3);
        }
        for (; j < nn; j++) {
            float c = sh_c[j];
            float2 x = __bfloat1622float2(g_Xb[(size_t)sh_i[j] * 64 + t]);
            ax = fmaf(c, x.x, ax); ay = fmaf(c, x.y, ay);
            wsum += c;
        }
    }
    float inv = (wsum > 0.f) ? 1.f / wsum : 0.f;
    *reinterpret_cast<float2*>(&g_A[(size_t)e * D + t * 2]) =
        make_float2(ax * inv, ay * inv);
}

// one block (64 threads) per node: out[n] += elu(mean_i Y[e_i])
__global__ void aggV_kernel(float* __restrict__ out) {
    int n = blockIdx.x, t = threadIdx.x;
    int beg = g_offV[n], end = g_offV[n + 1];
    __shared__ int sh_e[64];
    float ax = 0.f, ay = 0.f;
    for (int base = beg; base < end; base += 64) {
        int nn = min(64, end - base);
        __syncthreads();
        if (t < nn) sh_e[t] = g_sE[base + t];
        __syncthreads();
        int j = 0;
        for (; j + 4 <= nn; j += 4) {
            float2 y0 = __bfloat1622float2(g_Yb[(size_t)sh_e[j] * 64 + t]);
            float2 y1 = __bfloat1622float2(g_Yb[(size_t)sh_e[j + 1] * 64 + t]);
            float2 y2 = __bfloat1622float2(g_Yb[(size_t)sh_e[j + 2] * 64 + t]);
            float2 y3 = __bfloat1622float2(g_Yb[(size_t)sh_e[j + 3] * 64 + t]);
            ax += (y0.x + y1.x) + (y2.x + y3.x);
            ay += (y0.y + y1.y) + (y2.y + y3.y);
        }
        for (; j < nn; j++) {
            float2 y = __bfloat1622float2(g_Yb[(size_t)sh_e[j] * 64 + t]);
            ax += y.x; ay += y.y;
        }
    }
    int cnt = end - beg;
    float invc = 1.f / (float)(cnt > 0 ? cnt : 1);
    float xm0 = ax * invc, xm1 = ay * invc;
    xm0 = (xm0 > 0.f) ? xm0 : expm1f(xm0);
    xm1 = (xm1 > 0.f) ? xm1 : expm1f(xm1);
    float2* o2 = reinterpret_cast<float2*>(out + (size_t)n * D) + t;
    float2 o = *o2;
    o.x += xm0; o.y += xm1;
    *o2 = o;
}

// ---------------- launch -----------------------------------------------------
extern "C" void kernel_launch(void* const* d_in, const int* in_sizes, int n_in,
                              void* d_out, int out_size) {
    const float* X    = (const float*)d_in[0];
    const int*   V    = (const int*)d_in[1];
    const int*   E    = (const int*)d_in[2];
    const float* S    = (const float*)d_in[3];
    const float* Wx_w = (const float*)d_in[4];
    const float* Wx_b = (const float*)d_in[5];
    const float* Wv_w = (const float*)d_in[6];
    const float* Wv_b = (const float*)d_in[7];
    const float* a_w  = (const float*)d_in[8];
    const float* Wt_w = (const float*)d_in[9];
    const float* Wt_b = (const float*)d_in[10];
    float* out = (float*)d_out;

    float *pA = nullptr, *pZS = nullptr;
    void *pYb = nullptr;
    cudaGetSymbolAddress((void**)&pA,  g_A);
    cudaGetSymbolAddress((void**)&pZS, g_ZS);
    cudaGetSymbolAddress(&pYb, g_Yb);

    setup_kernel<<<392, 256>>>(a_w, Wv_w, Wv_b);
    mega1_kernel<<<HIST_BLOCKS + SCORE_BLOCKS + COPYS_BLOCKS, 256>>>(V, E, X, S);

    scan1_kernel<<<NBV + NBE, 1024>>>();
    scan23_kernel<<<S3V + S3E, 256>>>();

    scatter_kernel<<<(NNZV / 2 + 255) / 256, 256>>>(V, E);

    // X_init straight into the output buffer (fp32)
    gemm_tc_kernel<0, 0><<<(N_NODES + 127) / 128, 256>>>(X, D, Wx_w, Wx_b,
                                                         out, D, N_NODES, D);

    aggE_kernel<<<N_EDGES, 64>>>();

    // Z = elu(A @ Wv^T + Wv_b) into first 128 cols of g_ZS (ldc = 192)
    gemm_tc_kernel<1, 0><<<(N_EDGES + 127) / 128, 256>>>(pA, D, Wv_w, Wv_b,
                                                         pZS, DK, N_EDGES, D);

    // Y = [Z | S] @ Wt^T + Wt_b, written as bf16
    gemm_tc_kernel<0, 1><<<(N_EDGES + 127) / 128, 256>>>(pZS, DK, Wt_w, Wt_b,
                                                         pYb, D, N_EDGES, DK);

    aggV_kernel<<<N_NODES, 64>>>(out);
}

// round 14
// speedup vs baseline: 1.8997x; 1.0440x over previous
#include <cuda_runtime.h>
#include <cuda_bf16.h>
#include <math.h>

#define N_NODES 100000
#define N_EDGES 20000
#define NNZV    1600000
#define D       128
#define STAR    64
#define DK      (D + STAR)   // 192
#define NBV     98           // ceil(100000/1024)
#define NBE     20           // ceil(20000/1024)

// ---------------- scratch (device globals; no allocation allowed) ----------
__device__ __align__(16) float g_v[132];     // v[0..127] = Wv^T a, v[128] = a.Wv_b
__device__ float g_w[N_NODES];               // exp(leaky_relu(score)) per node
__device__ int   g_cntE[N_EDGES];
__device__ int   g_offE[N_EDGES + 1];
__device__ int   g_curE[N_EDGES];
__device__ int   g_cntV[N_NODES];
__device__ int   g_offV[N_NODES + 1];
__device__ int   g_curV[N_NODES];
__device__ int   g_bsV[NBV];
__device__ int   g_bsE[NBE];
__device__ int   g_sV[NNZV];                 // V values grouped by edge
__device__ int   g_sE[NNZV];                 // E values grouped by node
__device__ __align__(16) float g_A[N_EDGES * D];    // per-edge aggregated X (fp32)
__device__ __align__(16) float g_ZS[N_EDGES * DK];  // [elu(A@Wv^T+b) | S]
__device__ __align__(16) __nv_bfloat162 g_Xb[N_NODES * 64];  // X in bf16
__device__ __align__(16) __nv_bfloat162 g_Yb[N_EDGES * 64];  // Y in bf16

// ---------------- setup: zero counters + compute v -------------------------
__global__ void setup_kernel(const float* __restrict__ a_w,
                             const float* __restrict__ Wv_w,
                             const float* __restrict__ Wv_b) {
    int b = blockIdx.x;
    if (b < 391) {
        int i = b * 256 + threadIdx.x;
        if (i < N_NODES) g_cntV[i] = 0;
        if (i < N_EDGES) g_cntE[i] = 0;
    } else {
        int j = threadIdx.x;
        if (j < 128) {
            float s = 0.f;
            for (int k = 0; k < D; k++) s = fmaf(a_w[k], Wv_w[k * D + j], s);
            g_v[j] = s;
            if (j == 0) {
                float c = 0.f;
                for (int k = 0; k < D; k++) c = fmaf(a_w[k], Wv_b[k], c);
                g_v[128] = c;
            }
        }
    }
}

// ---------------- mega1: hist + copyS (score moved into gemm1) ---------------
#define HIST_BLOCKS  3125    // 2 incidences / thread
#define COPYS_BLOCKS 1250    // float4 per thread

__global__ void __launch_bounds__(256) mega1_kernel(
        const int* __restrict__ V, const int* __restrict__ E,
        const float* __restrict__ S) {
    int b = blockIdx.x;
    int tid = threadIdx.x;
    if (b < HIST_BLOCKS) {
        int i = b * 256 + tid;
        int2 v = reinterpret_cast<const int2*>(V)[i];
        int2 e = reinterpret_cast<const int2*>(E)[i];
        atomicAdd(&g_cntE[e.x], 1);
        atomicAdd(&g_cntE[e.y], 1);
        atomicAdd(&g_cntV[v.x], 1);
        atomicAdd(&g_cntV[v.y], 1);
    } else {
        // copy S into g_ZS cols [128,192): 4 floats / thread
        int idx4 = (b - HIST_BLOCKS) * 256 + tid;
        int e = idx4 >> 4;
        int j4 = (idx4 & 15) << 2;
        float4 val = *reinterpret_cast<const float4*>(&S[(size_t)e * STAR + j4]);
        *reinterpret_cast<float4*>(&g_ZS[(size_t)e * DK + D + j4]) = val;
    }
}

// ---------------- scan pass 1: block-local exclusive + block totals ----------
__device__ __forceinline__ void scan1_body(const int* __restrict__ cnt, int n,
                                           int* __restrict__ off,
                                           int* __restrict__ bsum, int blk) {
    __shared__ int wt[32];
    int tid = threadIdx.x, lane = tid & 31, wid = tid >> 5;
    int i = blk * 1024 + tid;
    int x = (i < n) ? cnt[i] : 0;
    int s = x;
    #pragma unroll
    for (int o = 1; o < 32; o <<= 1) {
        int t = __shfl_up_sync(0xffffffffu, s, o);
        if (lane >= o) s += t;
    }
    if (lane == 31) wt[wid] = s;
    __syncthreads();
    if (wid == 0) {
        int v = wt[lane];
        int vs = v;
        #pragma unroll
        for (int o = 1; o < 32; o <<= 1) {
            int t = __shfl_up_sync(0xffffffffu, vs, o);
            if (lane >= o) vs += t;
        }
        wt[lane] = vs - v;
    }
    __syncthreads();
    int ex = wt[wid] + s - x;
    if (i < n) off[i] = ex;
    if (tid == 1023) bsum[blk] = ex + x;
}

__global__ void scan1_kernel() {
    int b = blockIdx.x;
    if (b < NBV) scan1_body(g_cntV, N_NODES, g_offV, g_bsV, b);
    else scan1_body(g_cntE, N_EDGES, g_offE, g_bsE, b - NBV);
}

// ---------------- scan pass 2 (merged): add segment prefix, fill cur ---------
#define S3V 391   // ceil(100001/256)
#define S3E 79    // ceil(20001/256)
__global__ void __launch_bounds__(256) scan23_kernel() {
    __shared__ int sb[NBV];
    __shared__ int s_off, s_tot;
    int b = blockIdx.x;
    int tid = threadIdx.x;
    if (b < S3V) {
        if (tid < NBV) sb[tid] = g_bsV[tid];
        __syncthreads();
        if (tid == 0) {
            int my = b >> 2, o = 0, t = 0;
            for (int k = 0; k < NBV; k++) { if (k < my) o += sb[k]; t += sb[k]; }
            s_off = o; s_tot = t;
        }
        __syncthreads();
        int i = b * 256 + tid;
        if (i < N_NODES) {
            int v = g_offV[i] + s_off;
            g_offV[i] = v;
            g_curV[i] = v;
        } else if (i == N_NODES) g_offV[N_NODES] = s_tot;
    } else {
        int bb = b - S3V;
        if (tid < NBE) sb[tid] = g_bsE[tid];
        __syncthreads();
        if (tid == 0) {
            int my = bb >> 2, o = 0, t = 0;
            for (int k = 0; k < NBE; k++) { if (k < my) o += sb[k]; t += sb[k]; }
            s_off = o; s_tot = t;
        }
        __syncthreads();
        int i = bb * 256 + tid;
        if (i < N_EDGES) {
            int v = g_offE[i] + s_off;
            g_offE[i] = v;
            g_curE[i] = v;
        } else if (i == N_EDGES) g_offE[N_EDGES] = s_tot;
    }
}

__global__ void __launch_bounds__(256) scatter_kernel(const int* __restrict__ V,
                                                      const int* __restrict__ E) {
    int i = blockIdx.x * 256 + threadIdx.x;
    if (i >= NNZV / 2) return;
    int2 v = reinterpret_cast<const int2*>(V)[i];
    int2 e = reinterpret_cast<const int2*>(E)[i];
    int pe0 = atomicAdd(&g_curE[e.x], 1);
    g_sV[pe0] = v.x;
    int pe1 = atomicAdd(&g_curE[e.y], 1);
    g_sV[pe1] = v.y;
    int pv0 = atomicAdd(&g_curV[v.x], 1);
    g_sE[pv0] = e.x;
    int pv1 = atomicAdd(&g_curV[v.y], 1);
    g_sE[pv1] = e.y;
}

// ---------------- TF32 mma helpers ------------------------------------------
__device__ __forceinline__ unsigned f2tf(float f) {
    unsigned r;
    asm("cvt.rna.tf32.f32 %0, %1;" : "=r"(r) : "f"(f));
    return r;
}

__device__ __forceinline__ void mma_tf32(float c[4], const unsigned a[4],
                                         const unsigned b[2]) {
    asm volatile(
        "mma.sync.aligned.m16n8k8.row.col.f32.tf32.tf32.f32 "
        "{%0,%1,%2,%3}, {%4,%5,%6,%7}, {%8,%9}, {%0,%1,%2,%3};"
        : "+f"(c[0]), "+f"(c[1]), "+f"(c[2]), "+f"(c[3])
        : "r"(a[0]), "r"(a[1]), "r"(a[2]), "r"(a[3]), "r"(b[0]), "r"(b[1]));
}

#define AS_STRIDE 20
#define BS_STRIDE 136

// ---------------- gemm1 fused: X_init = X@Wx^T + b, plus Xb/bf16 + score -----
// Homogeneous: every block is a full GEMM tile; conversion + score ride the
// A-staging loads (X is touched exactly once on-chip for all three outputs).
__global__ void __launch_bounds__(256) gemm1_fused_kernel(
        const float* __restrict__ X,
        const float* __restrict__ Wx_w, const float* __restrict__ Wx_b,
        float* __restrict__ out) {
    __shared__ unsigned As[128 * AS_STRIDE];
    __shared__ unsigned Bs[16 * BS_STRIDE];
    const int tid = threadIdx.x, lane = tid & 31, warp = tid >> 5;
    const int wr = warp >> 2, wc = warp & 3;
    const int g = lane >> 2, tg = lane & 3;
    const int rowTile = blockIdx.x * 128;
    const int r = tid >> 1, cHalf = (tid & 1) * 8;
    const int gr = rowTile + r;

    float acc[4][4][4];
    #pragma unroll
    for (int mt = 0; mt < 4; mt++)
        #pragma unroll
        for (int nt = 0; nt < 4; nt++)
            #pragma unroll
            for (int q = 0; q < 4; q++) acc[mt][nt][q] = 0.f;

    float sacc = 0.f;   // partial score: dot(X[gr, my 64 cols], v)

    #pragma unroll
    for (int k0 = 0; k0 < D; k0 += 16) {
        {
            float4 v0 = make_float4(0.f, 0.f, 0.f, 0.f), v1 = v0;
            if (gr < N_NODES) {
                const float* p = X + (size_t)gr * D + k0 + cHalf;
                v0 = *reinterpret_cast<const float4*>(p);
                v1 = *reinterpret_cast<const float4*>(p + 4);
            }
            unsigned* dst = &As[r * AS_STRIDE + cHalf];
            dst[0] = f2tf(v0.x); dst[1] = f2tf(v0.y);
            dst[2] = f2tf(v0.z); dst[3] = f2tf(v0.w);
            dst[4] = f2tf(v1.x); dst[5] = f2tf(v1.y);
            dst[6] = f2tf(v1.z); dst[7] = f2tf(v1.w);
            if (gr < N_NODES) {
                // bf16 copy of the 8 staged values (bit-identical to old path)
                __nv_bfloat162 p0 = __float22bfloat162_rn(make_float2(v0.x, v0.y));
                __nv_bfloat162 p1 = __float22bfloat162_rn(make_float2(v0.z, v0.w));
                __nv_bfloat162 p2 = __float22bfloat162_rn(make_float2(v1.x, v1.y));
                __nv_bfloat162 p3 = __float22bfloat162_rn(make_float2(v1.z, v1.w));
                uint4 pk;
                pk.x = *reinterpret_cast<unsigned*>(&p0);
                pk.y = *reinterpret_cast<unsigned*>(&p1);
                pk.z = *reinterpret_cast<unsigned*>(&p2);
                pk.w = *reinterpret_cast<unsigned*>(&p3);
                *reinterpret_cast<uint4*>(&g_Xb[(size_t)gr * 64 + ((k0 + cHalf) >> 1)]) = pk;
                // score partial against v
                const float4* vv = reinterpret_cast<const float4*>(g_v + k0 + cHalf);
                float4 va = __ldg(vv), vb = __ldg(vv + 1);
                sacc = fmaf(v0.x, va.x, sacc);
                sacc = fmaf(v0.y, va.y, sacc);
                sacc = fmaf(v0.z, va.z, sacc);
                sacc = fmaf(v0.w, va.w, sacc);
                sacc = fmaf(v1.x, vb.x, sacc);
                sacc = fmaf(v1.y, vb.y, sacc);
                sacc = fmaf(v1.z, vb.z, sacc);
                sacc = fmaf(v1.w, vb.w, sacc);
            }
        }
        {
            int n = tid >> 1, c = (tid & 1) * 8;
            const float* p = Wx_w + (size_t)n * D + k0 + c;
            float4 v0 = *reinterpret_cast<const float4*>(p);
            float4 v1 = *reinterpret_cast<const float4*>(p + 4);
            Bs[(c + 0) * BS_STRIDE + n] = f2tf(v0.x);
            Bs[(c + 1) * BS_STRIDE + n] = f2tf(v0.y);
            Bs[(c + 2) * BS_STRIDE + n] = f2tf(v0.z);
            Bs[(c + 3) * BS_STRIDE + n] = f2tf(v0.w);
            Bs[(c + 4) * BS_STRIDE + n] = f2tf(v1.x);
            Bs[(c + 5) * BS_STRIDE + n] = f2tf(v1.y);
            Bs[(c + 6) * BS_STRIDE + n] = f2tf(v1.z);
            Bs[(c + 7) * BS_STRIDE + n] = f2tf(v1.w);
        }
        __syncthreads();
        #pragma unroll
        for (int ks = 0; ks < 16; ks += 8) {
            unsigned af[4][4], bf[4][2];
            #pragma unroll
            for (int mt = 0; mt < 4; mt++) {
                int r0 = (wr * 64 + mt * 16 + g) * AS_STRIDE;
                af[mt][0] = As[r0 + ks + tg];
                af[mt][1] = As[r0 + 8 * AS_STRIDE + ks + tg];
                af[mt][2] = As[r0 + ks + tg + 4];
                af[mt][3] = As[r0 + 8 * AS_STRIDE + ks + tg + 4];
            }
            #pragma unroll
            for (int nt = 0; nt < 4; nt++) {
                int n0 = wc * 32 + nt * 8 + g;
                bf[nt][0] = Bs[(ks + tg) * BS_STRIDE + n0];
                bf[nt][1] = Bs[(ks + tg + 4) * BS_STRIDE + n0];
            }
            #pragma unroll
            for (int mt = 0; mt < 4; mt++)
                #pragma unroll
                for (int nt = 0; nt < 4; nt++) mma_tf32(acc[mt][nt], af[mt], bf[nt]);
        }
        __syncthreads();
    }
    // finalize score: combine the two half-row partials (tid, tid^1)
    {
        float so = __shfl_xor_sync(0xffffffffu, sacc, 1);
        if ((tid & 1) == 0 && gr < N_NODES) {
            float s = sacc + so + g_v[128];
            s = (s >= 0.f) ? s : 0.2f * s;
            g_w[gr] = expf(s);
        }
    }
    // epilogue: X_init
    #pragma unroll
    for (int mt = 0; mt < 4; mt++) {
        int gr0 = rowTile + wr * 64 + mt * 16 + g;
        int gr1 = gr0 + 8;
        #pragma unroll
        for (int nt = 0; nt < 4; nt++) {
            int col = wc * 32 + nt * 8 + tg * 2;
            float b0 = __ldg(&Wx_b[col]), b1 = __ldg(&Wx_b[col + 1]);
            if (gr0 < N_NODES)
                *reinterpret_cast<float2*>(&out[(size_t)gr0 * D + col]) =
                    make_float2(acc[mt][nt][0] + b0, acc[mt][nt][1] + b1);
            if (gr1 < N_NODES)
                *reinterpret_cast<float2*>(&out[(size_t)gr1 * D + col]) =
                    make_float2(acc[mt][nt][2] + b0, acc[mt][nt][3] + b1);
        }
    }
}

// ---------------- generic TF32 GEMM (gemm2 / gemm3) --------------------------
// ACT: 0 none, 1 elu. BF16OUT: write bf16 (ldc in bf16 elems)
template <int ACT, int BF16OUT>
__global__ void gemm_tc_kernel(const float* __restrict__ A, int lda,
                               const float* __restrict__ W,
                               const float* __restrict__ bias,
                               void* __restrict__ Cv, int ldc,
                               int M, int K) {
    __shared__ unsigned As[128 * AS_STRIDE];
    __shared__ unsigned Bs[16 * BS_STRIDE];
    const int tid = threadIdx.x, lane = tid & 31, warp = tid >> 5;
    const int wr = warp >> 2, wc = warp & 3;
    const int g = lane >> 2, tg = lane & 3;
    const int rowTile = blockIdx.x * 128;

    float acc[4][4][4];
    #pragma unroll
    for (int mt = 0; mt < 4; mt++)
        #pragma unroll
        for (int nt = 0; nt < 4; nt++)
            #pragma unroll
            for (int q = 0; q < 4; q++) acc[mt][nt][q] = 0.f;

    for (int k0 = 0; k0 < K; k0 += 16) {
        {
            int r = tid >> 1, c = (tid & 1) * 8;
            int gr = rowTile + r;
            float4 v0 = make_float4(0.f, 0.f, 0.f, 0.f), v1 = v0;
            if (gr < M) {
                const float* p = A + (size_t)gr * lda + k0 + c;
                v0 = *reinterpret_cast<const float4*>(p);
                v1 = *reinterpret_cast<const float4*>(p + 4);
            }
            unsigned* dst = &As[r * AS_STRIDE + c];
            dst[0] = f2tf(v0.x); dst[1] = f2tf(v0.y);
            dst[2] = f2tf(v0.z); dst[3] = f2tf(v0.w);
            dst[4] = f2tf(v1.x); dst[5] = f2tf(v1.y);
            dst[6] = f2tf(v1.z); dst[7] = f2tf(v1.w);
        }
        {
            int n = tid >> 1, c = (tid & 1) * 8;
            const float* p = W + (size_t)n * K + k0 + c;
            float4 v0 = *reinterpret_cast<const float4*>(p);
            float4 v1 = *reinterpret_cast<const float4*>(p + 4);
            Bs[(c + 0) * BS_STRIDE + n] = f2tf(v0.x);
            Bs[(c + 1) * BS_STRIDE + n] = f2tf(v0.y);
            Bs[(c + 2) * BS_STRIDE + n] = f2tf(v0.z);
            Bs[(c + 3) * BS_STRIDE + n] = f2tf(v0.w);
            Bs[(c + 4) * BS_STRIDE + n] = f2tf(v1.x);
            Bs[(c + 5) * BS_STRIDE + n] = f2tf(v1.y);
            Bs[(c + 6) * BS_STRIDE + n] = f2tf(v1.z);
            Bs[(c + 7) * BS_STRIDE + n] = f2tf(v1.w);
        }
        __syncthreads();
        #pragma unroll
        for (int ks = 0; ks < 16; ks += 8) {
            unsigned af[4][4], bf[4][2];
            #pragma unroll
            for (int mt = 0; mt < 4; mt++) {
                int r0 = (wr * 64 + mt * 16 + g) * AS_STRIDE;
                af[mt][0] = As[r0 + ks + tg];
                af[mt][1] = As[r0 + 8 * AS_STRIDE + ks + tg];
                af[mt][2] = As[r0 + ks + tg + 4];
                af[mt][3] = As[r0 + 8 * AS_STRIDE + ks + tg + 4];
            }
            #pragma unroll
            for (int nt = 0; nt < 4; nt++) {
                int n0 = wc * 32 + nt * 8 + g;
                bf[nt][0] = Bs[(ks + tg) * BS_STRIDE + n0];
                bf[nt][1] = Bs[(ks + tg + 4) * BS_STRIDE + n0];
            }
            #pragma unroll
            for (int mt = 0; mt < 4; mt++)
                #pragma unroll
                for (int nt = 0; nt < 4; nt++) mma_tf32(acc[mt][nt], af[mt], bf[nt]);
        }
        __syncthreads();
    }
    #pragma unroll
    for (int mt = 0; mt < 4; mt++) {
        int gr0 = rowTile + wr * 64 + mt * 16 + g;
        int gr1 = gr0 + 8;
        #pragma unroll
        for (int nt = 0; nt < 4; nt++) {
            int col = wc * 32 + nt * 8 + tg * 2;
            float b0 = __ldg(&bias[col]), b1 = __ldg(&bias[col + 1]);
            float v0 = acc[mt][nt][0] + b0, v1 = acc[mt][nt][1] + b1;
            float v2 = acc[mt][nt][2] + b0, v3 = acc[mt][nt][3] + b1;
            if (ACT == 1) {
                v0 = (v0 > 0.f) ? v0 : expm1f(v0);
                v1 = (v1 > 0.f) ? v1 : expm1f(v1);
                v2 = (v2 > 0.f) ? v2 : expm1f(v2);
                v3 = (v3 > 0.f) ? v3 : expm1f(v3);
            }
            if (BF16OUT) {
                __nv_bfloat16* C = (__nv_bfloat16*)Cv;
                if (gr0 < M)
                    *reinterpret_cast<__nv_bfloat162*>(&C[(size_t)gr0 * ldc + col]) =
                        __float22bfloat162_rn(make_float2(v0, v1));
                if (gr1 < M)
                    *reinterpret_cast<__nv_bfloat162*>(&C[(size_t)gr1 * ldc + col]) =
                        __float22bfloat162_rn(make_float2(v2, v3));
            } else {
                float* C = (float*)Cv;
                if (gr0 < M)
                    *reinterpret_cast<float2*>(&C[(size_t)gr0 * ldc + col]) =
                        make_float2(v0, v1);
                if (gr1 < M)
                    *reinterpret_cast<float2*>(&C[(size_t)gr1 * ldc + col]) =
                        make_float2(v2, v3);
            }
        }
    }
}

// ---------------- segment aggregations (bf16 gathers) -----------------------
// one block (64 threads) per edge: A[e] = (sum w_i X[v_i]) / (sum w_i)
__global__ void aggE_kernel() {
    int e = blockIdx.x, t = threadIdx.x;
    int beg = g_offE[e], end = g_offE[e + 1];
    __shared__ int sh_i[64];
    __shared__ float sh_c[64];
    float ax = 0.f, ay = 0.f, wsum = 0.f;
    for (int base = beg; base < end; base += 64) {
        int nn = min(64, end - base);
        __syncthreads();
        if (t < nn) {
            int v = g_sV[base + t];
            sh_i[t] = v;
            sh_c[t] = g_w[v];
        }
        __syncthreads();
        int j = 0;
        for (; j + 4 <= nn; j += 4) {
            float c0 = sh_c[j], c1 = sh_c[j + 1], c2 = sh_c[j + 2], c3 = sh_c[j + 3];
            float2 x0 = __bfloat1622float2(g_Xb[(size_t)sh_i[j] * 64 + t]);
            float2 x1 = __bfloat1622float2(g_Xb[(size_t)sh_i[j + 1] * 64 + t]);
            float2 x2 = __bfloat1622float2(g_Xb[(size_t)sh_i[j + 2] * 64 + t]);
            float2 x3 = __bfloat1622float2(g_Xb[(size_t)sh_i[j + 3] * 64 + t]);
            ax = fmaf(c0, x0.x, ax); ay = fmaf(c0, x0.y, ay);
            ax = fmaf(c1, x1.x, ax); ay = fmaf(c1, x1.y, ay);
            ax = fmaf(c2, x2.x, ax); ay = fmaf(c2, x2.y, ay);
            ax = fmaf(c3, x3.x, ax); ay = fmaf(c3, x3.y, ay);
            wsum += (c0 + c1) + (c2 + c3);
        }
        for (; j < nn; j++) {
            float c = sh_c[j];
            float2 x = __bfloat1622float2(g_Xb[(size_t)sh_i[j] * 64 + t]);
            ax = fmaf(c, x.x, ax); ay = fmaf(c, x.y, ay);
            wsum += c;
        }
    }
    float inv = (wsum > 0.f) ? 1.f / wsum : 0.f;
    *reinterpret_cast<float2*>(&g_A[(size_t)e * D + t * 2]) =
        make_float2(ax * inv, ay * inv);
}

// one block (64 threads) per node: out[n] += elu(mean_i Y[e_i])
__global__ void aggV_kernel(float* __restrict__ out) {
    int n = blockIdx.x, t = threadIdx.x;
    int beg = g_offV[n], end = g_offV[n + 1];
    __shared__ int sh_e[64];
    float ax = 0.f, ay = 0.f;
    for (int base = beg; base < end; base += 64) {
        int nn = min(64, end - base);
        __syncthreads();
        if (t < nn) sh_e[t] = g_sE[base + t];
        __syncthreads();
        int j = 0;
        for (; j + 4 <= nn; j += 4) {
            float2 y0 = __bfloat1622float2(g_Yb[(size_t)sh_e[j] * 64 + t]);
            float2 y1 = __bfloat1622float2(g_Yb[(size_t)sh_e[j + 1] * 64 + t]);
            float2 y2 = __bfloat1622float2(g_Yb[(size_t)sh_e[j + 2] * 64 + t]);
            float2 y3 = __bfloat1622float2(g_Yb[(size_t)sh_e[j + 3] * 64 + t]);
            ax += (y0.x + y1.x) + (y2.x + y3.x);
            ay += (y0.y + y1.y) + (y2.y + y3.y);
        }
        for (; j < nn; j++) {
            float2 y = __bfloat1622float2(g_Yb[(size_t)sh_e[j] * 64 + t]);
            ax += y.x; ay += y.y;
        }
    }
    int cnt = end - beg;
    float invc = 1.f / (float)(cnt > 0 ? cnt : 1);
    float xm0 = ax * invc, xm1 = ay * invc;
    xm0 = (xm0 > 0.f) ? xm0 : expm1f(xm0);
    xm1 = (xm1 > 0.f) ? xm1 : expm1f(xm1);
    float2* o2 = reinterpret_cast<float2*>(out + (size_t)n * D) + t;
    float2 o = *o2;
    o.x += xm0; o.y += xm1;
    *o2 = o;
}

// ---------------- launch -----------------------------------------------------
extern "C" void kernel_launch(void* const* d_in, const int* in_sizes, int n_in,
                              void* d_out, int out_size) {
    const float* X    = (const float*)d_in[0];
    const int*   V    = (const int*)d_in[1];
    const int*   E    = (const int*)d_in[2];
    const float* S    = (const float*)d_in[3];
    const float* Wx_w = (const float*)d_in[4];
    const float* Wx_b = (const float*)d_in[5];
    const float* Wv_w = (const float*)d_in[6];
    const float* Wv_b = (const float*)d_in[7];
    const float* a_w  = (const float*)d_in[8];
    const float* Wt_w = (const float*)d_in[9];
    const float* Wt_b = (const float*)d_in[10];
    float* out = (float*)d_out;

    float *pA = nullptr, *pZS = nullptr;
    void *pYb = nullptr;
    cudaGetSymbolAddress((void**)&pA,  g_A);
    cudaGetSymbolAddress((void**)&pZS, g_ZS);
    cudaGetSymbolAddress(&pYb, g_Yb);

    // 1. zero counters + compute v
    setup_kernel<<<392, 256>>>(a_w, Wv_w, Wv_b);

    // 2. hist + copy S into g_ZS cols [128,192)
    mega1_kernel<<<HIST_BLOCKS + COPYS_BLOCKS, 256>>>(V, E, S);

    // 3-4. two-pass scan
    scan1_kernel<<<NBV + NBE, 1024>>>();
    scan23_kernel<<<S3V + S3E, 256>>>();

    // 5. counting-sort scatter
    scatter_kernel<<<(NNZV / 2 + 255) / 256, 256>>>(V, E);

    // 6. fused: X_init GEMM + bf16-X conversion + node scores (one X pass)
    gemm1_fused_kernel<<<(N_NODES + 127) / 128, 256>>>(X, Wx_w, Wx_b, out);

    // 7. per-edge weighted aggregation
    aggE_kernel<<<N_EDGES, 64>>>();

    // 8. Z = elu(A @ Wv^T + Wv_b) into first 128 cols of g_ZS (ldc = 192)
    gemm_tc_kernel<1, 0><<<(N_EDGES + 127) / 128, 256>>>(pA, D, Wv_w, Wv_b,
                                                         pZS, DK, N_EDGES, D);

    // 9. Y = [Z | S] @ Wt^T + Wt_b, written as bf16
    gemm_tc_kernel<0, 1><<<(N_EDGES + 127) / 128, 256>>>(pZS, DK, Wt_w, Wt_b,
                                                         pYb, D, N_EDGES, DK);

    // 10. per-node mean + elu + residual
    aggV_kernel<<<N_NODES, 64>>>(out);
}

// round 15
// speedup vs baseline: 1.9499x; 1.0264x over previous
#include <cuda_runtime.h>
#include <cuda_bf16.h>
#include <math.h>

#define N_NODES 100000
#define N_EDGES 20000
#define NNZV    1600000
#define D       128
#define STAR    64
#define NBV     98           // ceil(100000/1024)
#define NBE     20           // ceil(20000/1024)

// ---------------- scratch (device globals; no allocation allowed) ----------
__device__ __align__(16) float g_v[132];     // v[0..127] = Wv^T a, v[128] = a.Wv_b
__device__ float g_w[N_NODES];               // exp(leaky_relu(score)) per node
__device__ int   g_cntE[N_EDGES];
__device__ int   g_offE[N_EDGES + 1];
__device__ int   g_curE[N_EDGES];
__device__ int   g_cntV[N_NODES];
__device__ int   g_offV[N_NODES + 1];
__device__ int   g_curV[N_NODES];
__device__ int   g_bsV[NBV];
__device__ int   g_bsE[NBE];
__device__ int   g_sV[NNZV];                 // V values grouped by edge
__device__ int   g_sE[NNZV];                 // E values grouped by node
__device__ __align__(16) float g_A[N_EDGES * D];    // per-edge aggregated X (fp32)
__device__ __align__(16) float g_Ys[N_EDGES * D];   // S @ WtS^T + Wt_b
__device__ __align__(16) __nv_bfloat162 g_Xb[N_NODES * 64];  // X in bf16
__device__ __align__(16) __nv_bfloat162 g_Yb[N_EDGES * 64];  // Y in bf16

// ---------------- setup: zero counters + compute v -------------------------
__global__ void setup_kernel(const float* __restrict__ a_w,
                             const float* __restrict__ Wv_w,
                             const float* __restrict__ Wv_b) {
    int b = blockIdx.x;
    if (b < 391) {
        int i = b * 256 + threadIdx.x;
        if (i < N_NODES) g_cntV[i] = 0;
        if (i < N_EDGES) g_cntE[i] = 0;
    } else {
        int j = threadIdx.x;
        if (j < 128) {
            float s = 0.f;
            for (int k = 0; k < D; k++) s = fmaf(a_w[k], Wv_w[k * D + j], s);
            g_v[j] = s;
            if (j == 0) {
                float c = 0.f;
                for (int k = 0; k < D; k++) c = fmaf(a_w[k], Wv_b[k], c);
                g_v[128] = c;
            }
        }
    }
}

// ---------------- hist: 2 incidences / thread --------------------------------
#define HIST_BLOCKS 3125

__global__ void __launch_bounds__(256) hist_kernel(const int* __restrict__ V,
                                                   const int* __restrict__ E) {
    int i = blockIdx.x * 256 + threadIdx.x;
    int2 v = reinterpret_cast<const int2*>(V)[i];
    int2 e = reinterpret_cast<const int2*>(E)[i];
    atomicAdd(&g_cntE[e.x], 1);
    atomicAdd(&g_cntE[e.y], 1);
    atomicAdd(&g_cntV[v.x], 1);
    atomicAdd(&g_cntV[v.y], 1);
}

// ---------------- scan pass 1: block-local exclusive + block totals ----------
__device__ __forceinline__ void scan1_body(const int* __restrict__ cnt, int n,
                                           int* __restrict__ off,
                                           int* __restrict__ bsum, int blk) {
    __shared__ int wt[32];
    int tid = threadIdx.x, lane = tid & 31, wid = tid >> 5;
    int i = blk * 1024 + tid;
    int x = (i < n) ? cnt[i] : 0;
    int s = x;
    #pragma unroll
    for (int o = 1; o < 32; o <<= 1) {
        int t = __shfl_up_sync(0xffffffffu, s, o);
        if (lane >= o) s += t;
    }
    if (lane == 31) wt[wid] = s;
    __syncthreads();
    if (wid == 0) {
        int v = wt[lane];
        int vs = v;
        #pragma unroll
        for (int o = 1; o < 32; o <<= 1) {
            int t = __shfl_up_sync(0xffffffffu, vs, o);
            if (lane >= o) vs += t;
        }
        wt[lane] = vs - v;
    }
    __syncthreads();
    int ex = wt[wid] + s - x;
    if (i < n) off[i] = ex;
    if (tid == 1023) bsum[blk] = ex + x;
}

__global__ void scan1_kernel() {
    int b = blockIdx.x;
    if (b < NBV) scan1_body(g_cntV, N_NODES, g_offV, g_bsV, b);
    else scan1_body(g_cntE, N_EDGES, g_offE, g_bsE, b - NBV);
}

// ---------------- scan pass 2 (merged): add segment prefix, fill cur ---------
#define S3V 391   // ceil(100001/256)
#define S3E 79    // ceil(20001/256)
__global__ void __launch_bounds__(256) scan23_kernel() {
    __shared__ int sb[NBV];
    __shared__ int s_off, s_tot;
    int b = blockIdx.x;
    int tid = threadIdx.x;
    if (b < S3V) {
        if (tid < NBV) sb[tid] = g_bsV[tid];
        __syncthreads();
        if (tid == 0) {
            int my = b >> 2, o = 0, t = 0;
            for (int k = 0; k < NBV; k++) { if (k < my) o += sb[k]; t += sb[k]; }
            s_off = o; s_tot = t;
        }
        __syncthreads();
        int i = b * 256 + tid;
        if (i < N_NODES) {
            int v = g_offV[i] + s_off;
            g_offV[i] = v;
            g_curV[i] = v;
        } else if (i == N_NODES) g_offV[N_NODES] = s_tot;
    } else {
        int bb = b - S3V;
        if (tid < NBE) sb[tid] = g_bsE[tid];
        __syncthreads();
        if (tid == 0) {
            int my = bb >> 2, o = 0, t = 0;
            for (int k = 0; k < NBE; k++) { if (k < my) o += sb[k]; t += sb[k]; }
            s_off = o; s_tot = t;
        }
        __syncthreads();
        int i = bb * 256 + tid;
        if (i < N_EDGES) {
            int v = g_offE[i] + s_off;
            g_offE[i] = v;
            g_curE[i] = v;
        } else if (i == N_EDGES) g_offE[N_EDGES] = s_tot;
    }
}

__global__ void __launch_bounds__(256) scatter_kernel(const int* __restrict__ V,
                                                      const int* __restrict__ E) {
    int i = blockIdx.x * 256 + threadIdx.x;
    if (i >= NNZV / 2) return;
    int2 v = reinterpret_cast<const int2*>(V)[i];
    int2 e = reinterpret_cast<const int2*>(E)[i];
    int pe0 = atomicAdd(&g_curE[e.x], 1);
    g_sV[pe0] = v.x;
    int pe1 = atomicAdd(&g_curE[e.y], 1);
    g_sV[pe1] = v.y;
    int pv0 = atomicAdd(&g_curV[v.x], 1);
    g_sE[pv0] = e.x;
    int pv1 = atomicAdd(&g_curV[v.y], 1);
    g_sE[pv1] = e.y;
}

// ---------------- TF32 mma helpers ------------------------------------------
__device__ __forceinline__ unsigned f2tf(float f) {
    unsigned r;
    asm("cvt.rna.tf32.f32 %0, %1;" : "=r"(r) : "f"(f));
    return r;
}

__device__ __forceinline__ void mma_tf32(float c[4], const unsigned a[4],
                                         const unsigned b[2]) {
    asm volatile(
        "mma.sync.aligned.m16n8k8.row.col.f32.tf32.tf32.f32 "
        "{%0,%1,%2,%3}, {%4,%5,%6,%7}, {%8,%9}, {%0,%1,%2,%3};"
        : "+f"(c[0]), "+f"(c[1]), "+f"(c[2]), "+f"(c[3])
        : "r"(a[0]), "r"(a[1]), "r"(a[2]), "r"(a[3]), "r"(b[0]), "r"(b[1]));
}

#define AS_STRIDE 20
#define BS_STRIDE 136
#define ZS_STRIDE 132

// Generic 128-row-tile GEMM core: C[rowTile..+128, 0..127] = A@W^T + bias
template <int K>
__device__ __forceinline__ void gemm_core(
        const float* __restrict__ A, int lda,
        const float* __restrict__ W, int ldw,
        const float* __restrict__ bias,
        float* __restrict__ C, int ldc, int M, int rowTile,
        unsigned* As, unsigned* Bs) {
    const int tid = threadIdx.x, lane = tid & 31, warp = tid >> 5;
    const int wr = warp >> 2, wc = warp & 3;
    const int g = lane >> 2, tg = lane & 3;

    float acc[4][4][4];
    #pragma unroll
    for (int mt = 0; mt < 4; mt++)
        #pragma unroll
        for (int nt = 0; nt < 4; nt++)
            #pragma unroll
            for (int q = 0; q < 4; q++) acc[mt][nt][q] = 0.f;

    #pragma unroll
    for (int k0 = 0; k0 < K; k0 += 16) {
        {
            int r = tid >> 1, c = (tid & 1) * 8;
            int gr = rowTile + r;
            float4 v0 = make_float4(0.f, 0.f, 0.f, 0.f), v1 = v0;
            if (gr < M) {
                const float* p = A + (size_t)gr * lda + k0 + c;
                v0 = *reinterpret_cast<const float4*>(p);
                v1 = *reinterpret_cast<const float4*>(p + 4);
            }
            unsigned* dst = &As[r * AS_STRIDE + c];
            dst[0] = f2tf(v0.x); dst[1] = f2tf(v0.y);
            dst[2] = f2tf(v0.z); dst[3] = f2tf(v0.w);
            dst[4] = f2tf(v1.x); dst[5] = f2tf(v1.y);
            dst[6] = f2tf(v1.z); dst[7] = f2tf(v1.w);
        }
        {
            int n = tid >> 1, c = (tid & 1) * 8;
            const float* p = W + (size_t)n * ldw + k0 + c;
            float4 v0 = *reinterpret_cast<const float4*>(p);
            float4 v1 = *reinterpret_cast<const float4*>(p + 4);
            Bs[(c + 0) * BS_STRIDE + n] = f2tf(v0.x);
            Bs[(c + 1) * BS_STRIDE + n] = f2tf(v0.y);
            Bs[(c + 2) * BS_STRIDE + n] = f2tf(v0.z);
            Bs[(c + 3) * BS_STRIDE + n] = f2tf(v0.w);
            Bs[(c + 4) * BS_STRIDE + n] = f2tf(v1.x);
            Bs[(c + 5) * BS_STRIDE + n] = f2tf(v1.y);
            Bs[(c + 6) * BS_STRIDE + n] = f2tf(v1.z);
            Bs[(c + 7) * BS_STRIDE + n] = f2tf(v1.w);
        }
        __syncthreads();
        #pragma unroll
        for (int ks = 0; ks < 16; ks += 8) {
            unsigned af[4][4], bf[4][2];
            #pragma unroll
            for (int mt = 0; mt < 4; mt++) {
                int r0 = (wr * 64 + mt * 16 + g) * AS_STRIDE;
                af[mt][0] = As[r0 + ks + tg];
                af[mt][1] = As[r0 + 8 * AS_STRIDE + ks + tg];
                af[mt][2] = As[r0 + ks + tg + 4];
                af[mt][3] = As[r0 + 8 * AS_STRIDE + ks + tg + 4];
            }
            #pragma unroll
            for (int nt = 0; nt < 4; nt++) {
                int n0 = wc * 32 + nt * 8 + g;
                bf[nt][0] = Bs[(ks + tg) * BS_STRIDE + n0];
                bf[nt][1] = Bs[(ks + tg + 4) * BS_STRIDE + n0];
            }
            #pragma unroll
            for (int mt = 0; mt < 4; mt++)
                #pragma unroll
                for (int nt = 0; nt < 4; nt++) mma_tf32(acc[mt][nt], af[mt], bf[nt]);
        }
        __syncthreads();
    }
    #pragma unroll
    for (int mt = 0; mt < 4; mt++) {
        int gr0 = rowTile + wr * 64 + mt * 16 + g;
        int gr1 = gr0 + 8;
        #pragma unroll
        for (int nt = 0; nt < 4; nt++) {
            int col = wc * 32 + nt * 8 + tg * 2;
            float b0 = __ldg(&bias[col]), b1 = __ldg(&bias[col + 1]);
            if (gr0 < M)
                *reinterpret_cast<float2*>(&C[(size_t)gr0 * ldc + col]) =
                    make_float2(acc[mt][nt][0] + b0, acc[mt][nt][1] + b1);
            if (gr1 < M)
                *reinterpret_cast<float2*>(&C[(size_t)gr1 * ldc + col]) =
                    make_float2(acc[mt][nt][2] + b0, acc[mt][nt][3] + b1);
        }
    }
}

// ---------------- gemm1 fused: X_init + Xb/bf16 + score, plus Ys blocks ------
// blocks [0, GEMM1_BLOCKS): fused X pass (X_init GEMM + bf16 convert + score)
// blocks [GEMM1_BLOCKS, +YS_BLOCKS): Ys = S @ WtS^T + Wt_b  (homogeneous GEMM)
#define GEMM1_BLOCKS 782     // ceil(100000/128)
#define YS_BLOCKS    157     // ceil(20000/128)

__global__ void __launch_bounds__(256) gemm1_fused_kernel(
        const float* __restrict__ X,
        const float* __restrict__ Wx_w, const float* __restrict__ Wx_b,
        const float* __restrict__ S,
        const float* __restrict__ Wt_w, const float* __restrict__ Wt_b,
        float* __restrict__ out) {
    __shared__ unsigned As[128 * AS_STRIDE];
    __shared__ unsigned Bs[16 * BS_STRIDE];
    if (blockIdx.x >= GEMM1_BLOCKS) {
        // Ys branch (full GEMM tile, identical resource shape)
        gemm_core<64>(S, STAR, Wt_w + 128, 192, Wt_b, g_Ys, D, N_EDGES,
                      (blockIdx.x - GEMM1_BLOCKS) * 128, As, Bs);
        return;
    }
    const int tid = threadIdx.x, lane = tid & 31, warp = tid >> 5;
    const int wr = warp >> 2, wc = warp & 3;
    const int g = lane >> 2, tg = lane & 3;
    const int rowTile = blockIdx.x * 128;
    const int r = tid >> 1, cHalf = (tid & 1) * 8;
    const int gr = rowTile + r;

    float acc[4][4][4];
    #pragma unroll
    for (int mt = 0; mt < 4; mt++)
        #pragma unroll
        for (int nt = 0; nt < 4; nt++)
            #pragma unroll
            for (int q = 0; q < 4; q++) acc[mt][nt][q] = 0.f;

    float sacc = 0.f;   // partial score: dot(X[gr, my 64 cols], v)

    #pragma unroll
    for (int k0 = 0; k0 < D; k0 += 16) {
        {
            float4 v0 = make_float4(0.f, 0.f, 0.f, 0.f), v1 = v0;
            if (gr < N_NODES) {
                const float* p = X + (size_t)gr * D + k0 + cHalf;
                v0 = *reinterpret_cast<const float4*>(p);
                v1 = *reinterpret_cast<const float4*>(p + 4);
            }
            unsigned* dst = &As[r * AS_STRIDE + cHalf];
            dst[0] = f2tf(v0.x); dst[1] = f2tf(v0.y);
            dst[2] = f2tf(v0.z); dst[3] = f2tf(v0.w);
            dst[4] = f2tf(v1.x); dst[5] = f2tf(v1.y);
            dst[6] = f2tf(v1.z); dst[7] = f2tf(v1.w);
            if (gr < N_NODES) {
                __nv_bfloat162 p0 = __float22bfloat162_rn(make_float2(v0.x, v0.y));
                __nv_bfloat162 p1 = __float22bfloat162_rn(make_float2(v0.z, v0.w));
                __nv_bfloat162 p2 = __float22bfloat162_rn(make_float2(v1.x, v1.y));
                __nv_bfloat162 p3 = __float22bfloat162_rn(make_float2(v1.z, v1.w));
                uint4 pk;
                pk.x = *reinterpret_cast<unsigned*>(&p0);
                pk.y = *reinterpret_cast<unsigned*>(&p1);
                pk.z = *reinterpret_cast<unsigned*>(&p2);
                pk.w = *reinterpret_cast<unsigned*>(&p3);
                *reinterpret_cast<uint4*>(&g_Xb[(size_t)gr * 64 + ((k0 + cHalf) >> 1)]) = pk;
                const float4* vv = reinterpret_cast<const float4*>(g_v + k0 + cHalf);
                float4 va = __ldg(vv), vb = __ldg(vv + 1);
                sacc = fmaf(v0.x, va.x, sacc);
                sacc = fmaf(v0.y, va.y, sacc);
                sacc = fmaf(v0.z, va.z, sacc);
                sacc = fmaf(v0.w, va.w, sacc);
                sacc = fmaf(v1.x, vb.x, sacc);
                sacc = fmaf(v1.y, vb.y, sacc);
                sacc = fmaf(v1.z, vb.z, sacc);
                sacc = fmaf(v1.w, vb.w, sacc);
            }
        }
        {
            int n = tid >> 1, c = (tid & 1) * 8;
            const float* p = Wx_w + (size_t)n * D + k0 + c;
            float4 v0 = *reinterpret_cast<const float4*>(p);
            float4 v1 = *reinterpret_cast<const float4*>(p + 4);
            Bs[(c + 0) * BS_STRIDE + n] = f2tf(v0.x);
            Bs[(c + 1) * BS_STRIDE + n] = f2tf(v0.y);
            Bs[(c + 2) * BS_STRIDE + n] = f2tf(v0.z);
            Bs[(c + 3) * BS_STRIDE + n] = f2tf(v0.w);
            Bs[(c + 4) * BS_STRIDE + n] = f2tf(v1.x);
            Bs[(c + 5) * BS_STRIDE + n] = f2tf(v1.y);
            Bs[(c + 6) * BS_STRIDE + n] = f2tf(v1.z);
            Bs[(c + 7) * BS_STRIDE + n] = f2tf(v1.w);
        }
        __syncthreads();
        #pragma unroll
        for (int ks = 0; ks < 16; ks += 8) {
            unsigned af[4][4], bf[4][2];
            #pragma unroll
            for (int mt = 0; mt < 4; mt++) {
                int r0 = (wr * 64 + mt * 16 + g) * AS_STRIDE;
                af[mt][0] = As[r0 + ks + tg];
                af[mt][1] = As[r0 + 8 * AS_STRIDE + ks + tg];
                af[mt][2] = As[r0 + ks + tg + 4];
                af[mt][3] = As[r0 + 8 * AS_STRIDE + ks + tg + 4];
            }
            #pragma unroll
            for (int nt = 0; nt < 4; nt++) {
                int n0 = wc * 32 + nt * 8 + g;
                bf[nt][0] = Bs[(ks + tg) * BS_STRIDE + n0];
                bf[nt][1] = Bs[(ks + tg + 4) * BS_STRIDE + n0];
            }
            #pragma unroll
            for (int mt = 0; mt < 4; mt++)
                #pragma unroll
                for (int nt = 0; nt < 4; nt++) mma_tf32(acc[mt][nt], af[mt], bf[nt]);
        }
        __syncthreads();
    }
    // finalize score: combine the two half-row partials (tid, tid^1)
    {
        float so = __shfl_xor_sync(0xffffffffu, sacc, 1);
        if ((tid & 1) == 0 && gr < N_NODES) {
            float s = sacc + so + g_v[128];
            s = (s >= 0.f) ? s : 0.2f * s;
            g_w[gr] = expf(s);
        }
    }
    // epilogue: X_init
    #pragma unroll
    for (int mt = 0; mt < 4; mt++) {
        int gr0 = rowTile + wr * 64 + mt * 16 + g;
        int gr1 = gr0 + 8;
        #pragma unroll
        for (int nt = 0; nt < 4; nt++) {
            int col = wc * 32 + nt * 8 + tg * 2;
            float b0 = __ldg(&Wx_b[col]), b1 = __ldg(&Wx_b[col + 1]);
            if (gr0 < N_NODES)
                *reinterpret_cast<float2*>(&out[(size_t)gr0 * D + col]) =
                    make_float2(acc[mt][nt][0] + b0, acc[mt][nt][1] + b1);
            if (gr1 < N_NODES)
                *reinterpret_cast<float2*>(&out[(size_t)gr1 * D + col]) =
                    make_float2(acc[mt][nt][2] + b0, acc[mt][nt][3] + b1);
        }
    }
}

// ---------------- aggE: one block (64 thr) per edge --------------------------
__global__ void aggE_kernel() {
    int e = blockIdx.x, t = threadIdx.x;
    int beg = g_offE[e], end = g_offE[e + 1];
    __shared__ int sh_i[64];
    __shared__ float sh_c[64];
    float ax = 0.f, ay = 0.f, wsum = 0.f;
    for (int base = beg; base < end; base += 64) {
        int nn = min(64, end - base);
        __syncthreads();
        if (t < nn) {
            int v = g_sV[base + t];
            sh_i[t] = v;
            sh_c[t] = g_w[v];
        }
        __syncthreads();
        int j = 0;
        for (; j + 4 <= nn; j += 4) {
            float c0 = sh_c[j], c1 = sh_c[j + 1], c2 = sh_c[j + 2], c3 = sh_c[j + 3];
            float2 x0 = __bfloat1622float2(g_Xb[(size_t)sh_i[j] * 64 + t]);
            float2 x1 = __bfloat1622float2(g_Xb[(size_t)sh_i[j + 1] * 64 + t]);
            float2 x2 = __bfloat1622float2(g_Xb[(size_t)sh_i[j + 2] * 64 + t]);
            float2 x3 = __bfloat1622float2(g_Xb[(size_t)sh_i[j + 3] * 64 + t]);
            ax = fmaf(c0, x0.x, ax); ay = fmaf(c0, x0.y, ay);
            ax = fmaf(c1, x1.x, ax); ay = fmaf(c1, x1.y, ay);
            ax = fmaf(c2, x2.x, ax); ay = fmaf(c2, x2.y, ay);
            ax = fmaf(c3, x3.x, ax); ay = fmaf(c3, x3.y, ay);
            wsum += (c0 + c1) + (c2 + c3);
        }
        for (; j < nn; j++) {
            float c = sh_c[j];
            float2 x = __bfloat1622float2(g_Xb[(size_t)sh_i[j] * 64 + t]);
            ax = fmaf(c, x.x, ax); ay = fmaf(c, x.y, ay);
            wsum += c;
        }
    }
    float inv = (wsum > 0.f) ? 1.f / wsum : 0.f;
    *reinterpret_cast<float2*>(&g_A[(size_t)e * D + t * 2]) =
        make_float2(ax * inv, ay * inv);
}

// ---------------- fused edge MLP: Y = elu(A@Wv^T+b)@WtZ^T + Ys -> bf16 -------
// Z (tf32) lives in dynamic smem between the two MMA stages.
__global__ void __launch_bounds__(256) gemm23_kernel(
        const float* __restrict__ Wv_w, const float* __restrict__ Wv_b,
        const float* __restrict__ Wt_w) {
    extern __shared__ unsigned sm[];
    unsigned* Zs = sm;                      // 128 x ZS_STRIDE
    unsigned* As = sm;                      // aliases Zs (stage-1 only)
    unsigned* Bs = sm + 128 * ZS_STRIDE;    // 16 x BS_STRIDE
    const int tid = threadIdx.x, lane = tid & 31, warp = tid >> 5;
    const int wr = warp >> 2, wc = warp & 3;
    const int g = lane >> 2, tg = lane & 3;
    const int rowTile = blockIdx.x * 128;

    float acc[4][4][4];
    #pragma unroll
    for (int mt = 0; mt < 4; mt++)
        #pragma unroll
        for (int nt = 0; nt < 4; nt++)
            #pragma unroll
            for (int q = 0; q < 4; q++) acc[mt][nt][q] = 0.f;

    // stage 1: acc = A @ Wv^T
    #pragma unroll
    for (int k0 = 0; k0 < 128; k0 += 16) {
        {
            int r = tid >> 1, c = (tid & 1) * 8;
            int gr = rowTile + r;
            float4 v0 = make_float4(0.f, 0.f, 0.f, 0.f), v1 = v0;
            if (gr < N_EDGES) {
                const float* p = g_A + (size_t)gr * D + k0 + c;
                v0 = *reinterpret_cast<const float4*>(p);
                v1 = *reinterpret_cast<const float4*>(p + 4);
            }
            unsigned* dst = &As[r * AS_STRIDE + c];
            dst[0] = f2tf(v0.x); dst[1] = f2tf(v0.y);
            dst[2] = f2tf(v0.z); dst[3] = f2tf(v0.w);
            dst[4] = f2tf(v1.x); dst[5] = f2tf(v1.y);
            dst[6] = f2tf(v1.z); dst[7] = f2tf(v1.w);
        }
        {
            int n = tid >> 1, c = (tid & 1) * 8;
            const float* p = Wv_w + (size_t)n * D + k0 + c;
            float4 v0 = *reinterpret_cast<const float4*>(p);
            float4 v1 = *reinterpret_cast<const float4*>(p + 4);
            Bs[(c + 0) * BS_STRIDE + n] = f2tf(v0.x);
            Bs[(c + 1) * BS_STRIDE + n] = f2tf(v0.y);
            Bs[(c + 2) * BS_STRIDE + n] = f2tf(v0.z);
            Bs[(c + 3) * BS_STRIDE + n] = f2tf(v0.w);
            Bs[(c + 4) * BS_STRIDE + n] = f2tf(v1.x);
            Bs[(c + 5) * BS_STRIDE + n] = f2tf(v1.y);
            Bs[(c + 6) * BS_STRIDE + n] = f2tf(v1.z);
            Bs[(c + 7) * BS_STRIDE + n] = f2tf(v1.w);
        }
        __syncthreads();
        #pragma unroll
        for (int ks = 0; ks < 16; ks += 8) {
            unsigned af[4][4], bf[4][2];
            #pragma unroll
            for (int mt = 0; mt < 4; mt++) {
                int r0 = (wr * 64 + mt * 16 + g) * AS_STRIDE;
                af[mt][0] = As[r0 + ks + tg];
                af[mt][1] = As[r0 + 8 * AS_STRIDE + ks + tg];
                af[mt][2] = As[r0 + ks + tg + 4];
                af[mt][3] = As[r0 + 8 * AS_STRIDE + ks + tg + 4];
            }
            #pragma unroll
            for (int nt = 0; nt < 4; nt++) {
                int n0 = wc * 32 + nt * 8 + g;
                bf[nt][0] = Bs[(ks + tg) * BS_STRIDE + n0];
                bf[nt][1] = Bs[(ks + tg + 4) * BS_STRIDE + n0];
            }
            #pragma unroll
            for (int mt = 0; mt < 4; mt++)
                #pragma unroll
                for (int nt = 0; nt < 4; nt++) mma_tf32(acc[mt][nt], af[mt], bf[nt]);
        }
        __syncthreads();
    }
    // epilogue 1: Z = elu(acc + Wv_b) -> Zs (tf32 in smem)
    #pragma unroll
    for (int mt = 0; mt < 4; mt++) {
        int r0 = wr * 64 + mt * 16 + g;
        int r1 = r0 + 8;
        #pragma unroll
        for (int nt = 0; nt < 4; nt++) {
            int col = wc * 32 + nt * 8 + tg * 2;
            float b0 = __ldg(&Wv_b[col]), b1 = __ldg(&Wv_b[col + 1]);
            float v0 = acc[mt][nt][0] + b0, v1 = acc[mt][nt][1] + b1;
            float v2 = acc[mt][nt][2] + b0, v3 = acc[mt][nt][3] + b1;
            v0 = (v0 > 0.f) ? v0 : expm1f(v0);
            v1 = (v1 > 0.f) ? v1 : expm1f(v1);
            v2 = (v2 > 0.f) ? v2 : expm1f(v2);
            v3 = (v3 > 0.f) ? v3 : expm1f(v3);
            Zs[r0 * ZS_STRIDE + col]     = f2tf(v0);
            Zs[r0 * ZS_STRIDE + col + 1] = f2tf(v1);
            Zs[r1 * ZS_STRIDE + col]     = f2tf(v2);
            Zs[r1 * ZS_STRIDE + col + 1] = f2tf(v3);
        }
    }
    // stage 2: acc = Z @ WtZ^T  (WtZ = first 128 cols of Wt, row stride 192)
    #pragma unroll
    for (int mt = 0; mt < 4; mt++)
        #pragma unroll
        for (int nt = 0; nt < 4; nt++)
            #pragma unroll
            for (int q = 0; q < 4; q++) acc[mt][nt][q] = 0.f;
    #pragma unroll
    for (int k0 = 0; k0 < 128; k0 += 16) {
        {
            int n = tid >> 1, c = (tid & 1) * 8;
            const float* p = Wt_w + (size_t)n * 192 + k0 + c;
            float4 v0 = *reinterpret_cast<const float4*>(p);
            float4 v1 = *reinterpret_cast<const float4*>(p + 4);
            Bs[(c + 0) * BS_STRIDE + n] = f2tf(v0.x);
            Bs[(c + 1) * BS_STRIDE + n] = f2tf(v0.y);
            Bs[(c + 2) * BS_STRIDE + n] = f2tf(v0.z);
            Bs[(c + 3) * BS_STRIDE + n] = f2tf(v0.w);
            Bs[(c + 4) * BS_STRIDE + n] = f2tf(v1.x);
            Bs[(c + 5) * BS_STRIDE + n] = f2tf(v1.y);
            Bs[(c + 6) * BS_STRIDE + n] = f2tf(v1.z);
            Bs[(c + 7) * BS_STRIDE + n] = f2tf(v1.w);
        }
        __syncthreads();
        #pragma unroll
        for (int ks = 0; ks < 16; ks += 8) {
            unsigned af[4][4], bf[4][2];
            #pragma unroll
            for (int mt = 0; mt < 4; mt++) {
                int r0 = (wr * 64 + mt * 16 + g) * ZS_STRIDE;
                af[mt][0] = Zs[r0 + k0 + ks + tg];
                af[mt][1] = Zs[r0 + 8 * ZS_STRIDE + k0 + ks + tg];
                af[mt][2] = Zs[r0 + k0 + ks + tg + 4];
                af[mt][3] = Zs[r0 + 8 * ZS_STRIDE + k0 + ks + tg + 4];
            }
            #pragma unroll
            for (int nt = 0; nt < 4; nt++) {
                int n0 = wc * 32 + nt * 8 + g;
                bf[nt][0] = Bs[(ks + tg) * BS_STRIDE + n0];
                bf[nt][1] = Bs[(ks + tg + 4) * BS_STRIDE + n0];
            }
            #pragma unroll
            for (int mt = 0; mt < 4; mt++)
                #pragma unroll
                for (int nt = 0; nt < 4; nt++) mma_tf32(acc[mt][nt], af[mt], bf[nt]);
        }
        __syncthreads();
    }
    // epilogue 2: Y = acc + Ys -> bf16
    #pragma unroll
    for (int mt = 0; mt < 4; mt++) {
        int gr0 = rowTile + wr * 64 + mt * 16 + g;
        int gr1 = gr0 + 8;
        #pragma unroll
        for (int nt = 0; nt < 4; nt++) {
            int col = wc * 32 + nt * 8 + tg * 2;
            if (gr0 < N_EDGES) {
                float2 ys = *reinterpret_cast<const float2*>(&g_Ys[(size_t)gr0 * D + col]);
                g_Yb[(size_t)gr0 * 64 + (col >> 1)] = __float22bfloat162_rn(
                    make_float2(acc[mt][nt][0] + ys.x, acc[mt][nt][1] + ys.y));
            }
            if (gr1 < N_EDGES) {
                float2 ys = *reinterpret_cast<const float2*>(&g_Ys[(size_t)gr1 * D + col]);
                g_Yb[(size_t)gr1 * 64 + (col >> 1)] = __float22bfloat162_rn(
                    make_float2(acc[mt][nt][2] + ys.x, acc[mt][nt][3] + ys.y));
            }
        }
    }
}

// ---------------- aggV: one block (64 thr) per node --------------------------
__global__ void aggV_kernel(float* __restrict__ out) {
    int n = blockIdx.x, t = threadIdx.x;
    int beg = g_offV[n], end = g_offV[n + 1];
    __shared__ int sh_e[64];
    float ax = 0.f, ay = 0.f;
    for (int base = beg; base < end; base += 64) {
        int nn = min(64, end - base);
        __syncthreads();
        if (t < nn) sh_e[t] = g_sE[base + t];
        __syncthreads();
        int j = 0;
        for (; j + 4 <= nn; j += 4) {
            float2 y0 = __bfloat1622float2(g_Yb[(size_t)sh_e[j] * 64 + t]);
            float2 y1 = __bfloat1622float2(g_Yb[(size_t)sh_e[j + 1] * 64 + t]);
            float2 y2 = __bfloat1622float2(g_Yb[(size_t)sh_e[j + 2] * 64 + t]);
            float2 y3 = __bfloat1622float2(g_Yb[(size_t)sh_e[j + 3] * 64 + t]);
            ax += (y0.x + y1.x) + (y2.x + y3.x);
            ay += (y0.y + y1.y) + (y2.y + y3.y);
        }
        for (; j < nn; j++) {
            float2 y = __bfloat1622float2(g_Yb[(size_t)sh_e[j] * 64 + t]);
            ax += y.x; ay += y.y;
        }
    }
    int cnt = end - beg;
    float invc = 1.f / (float)(cnt > 0 ? cnt : 1);
    float xm0 = ax * invc, xm1 = ay * invc;
    xm0 = (xm0 > 0.f) ? xm0 : expm1f(xm0);
    xm1 = (xm1 > 0.f) ? xm1 : expm1f(xm1);
    float2* o2 = reinterpret_cast<float2*>(out + (size_t)n * D) + t;
    float2 o = *o2;
    o.x += xm0; o.y += xm1;
    *o2 = o;
}

// ---------------- launch -----------------------------------------------------
#define GEMM23_SMEM ((128 * ZS_STRIDE + 16 * BS_STRIDE) * 4)

extern "C" void kernel_launch(void* const* d_in, const int* in_sizes, int n_in,
                              void* d_out, int out_size) {
    const float* X    = (const float*)d_in[0];
    const int*   V    = (const int*)d_in[1];
    const int*   E    = (const int*)d_in[2];
    const float* S    = (const float*)d_in[3];
    const float* Wx_w = (const float*)d_in[4];
    const float* Wx_b = (const float*)d_in[5];
    const float* Wv_w = (const float*)d_in[6];
    const float* Wv_b = (const float*)d_in[7];
    const float* a_w  = (const float*)d_in[8];
    const float* Wt_w = (const float*)d_in[9];
    const float* Wt_b = (const float*)d_in[10];
    float* out = (float*)d_out;

    cudaFuncSetAttribute(gemm23_kernel,
                         cudaFuncAttributeMaxDynamicSharedMemorySize, GEMM23_SMEM);

    // 1. zero counters + compute v
    setup_kernel<<<392, 256>>>(a_w, Wv_w, Wv_b);

    // 2. incidence histograms
    hist_kernel<<<HIST_BLOCKS, 256>>>(V, E);

    // 3-4. two-pass scan
    scan1_kernel<<<NBV + NBE, 1024>>>();
    scan23_kernel<<<S3V + S3E, 256>>>();

    // 5. counting-sort scatter
    scatter_kernel<<<(NNZV / 2 + 255) / 256, 256>>>(V, E);

    // 6. fused X pass (X_init + bf16 X + scores) + Ys GEMM (homogeneous)
    gemm1_fused_kernel<<<GEMM1_BLOCKS + YS_BLOCKS, 256>>>(X, Wx_w, Wx_b,
                                                          S, Wt_w, Wt_b, out);

    // 7. per-edge weighted aggregation
    aggE_kernel<<<N_EDGES, 64>>>();

    // 8. fused edge MLP: Y = elu(A@Wv^T+b)@WtZ^T + Ys -> bf16
    gemm23_kernel<<<157, 256, GEMM23_SMEM>>>(Wv_w, Wv_b, Wt_w);

    // 9. per-node mean + elu + residual
    aggV_kernel<<<N_NODES, 64>>>(out);
}